// round 1
// baseline (speedup 1.0000x reference)
#include <cuda_runtime.h>

#define LDIM 512
#define CDIM 128
#define NROWS (LDIM * LDIM)   // 262144 pair rows
#define EPSV 1e-5f

// ---------------- scratch (static device memory; no runtime allocation) ----
__device__ float d_zln[(size_t)NROWS * CDIM];   // layernormed z, [n][c]
__device__ float d_g  [(size_t)NROWS * CDIM];   // sigmoid(zln @ W_gate_out), [n][c]
__device__ float d_at [(size_t)CDIM * NROWS];   // a transposed: [c][i][k]
__device__ float d_bt [(size_t)CDIM * NROWS];   // b transposed: [c][j][k]
__device__ float d_mt [(size_t)CDIM * NROWS];   // einsum result: [c][i][j]

__device__ __forceinline__ float warp_sum(float v) {
#pragma unroll
  for (int o = 16; o > 0; o >>= 1) v += __shfl_xor_sync(0xffffffffu, v, o);
  return v;
}
__device__ __forceinline__ float sigmoidf(float x) {
  return 1.f / (1.f + __expf(-x));
}

// ---------------- K0: LayerNorm of z over channel dim ----------------------
__global__ __launch_bounds__(256) void k_ln_in(const float* __restrict__ z,
                                               const float* __restrict__ w,
                                               const float* __restrict__ b) {
  int warp = threadIdx.x >> 5, lane = threadIdx.x & 31;
  size_t row = (size_t)blockIdx.x * 8 + warp;
  const float4 v = *(const float4*)(z + row * CDIM + lane * 4);
  float mu = warp_sum(v.x + v.y + v.z + v.w) * (1.f / CDIM);
  float dx = v.x - mu, dy = v.y - mu, dz = v.z - mu, dw = v.w - mu;
  float var = warp_sum(dx * dx + dy * dy + dz * dz + dw * dw) * (1.f / CDIM);
  float rstd = rsqrtf(var + EPSV);
  float4 wv = *(const float4*)(w + lane * 4);
  float4 bv = *(const float4*)(b + lane * 4);
  float4 o = make_float4(dx * rstd * wv.x + bv.x, dy * rstd * wv.y + bv.y,
                         dz * rstd * wv.z + bv.z, dw * rstd * wv.w + bv.w);
  *(float4*)(d_zln + row * CDIM + lane * 4) = o;
}

// ---------------- K1: projections + gates -----------------------------------
// Block: 64 rows x 128 cols, K=128 fully resident A-tile in smem.
// Thread (tx in [0,32), ty in [0,8)) owns 8 rows x 4 cols.
__device__ __forceinline__ void gemm_pair(const float* __restrict__ As, int tx, int ty,
                                          const float* __restrict__ Wg,
                                          const float* __restrict__ Wp,
                                          float accg[8][4], float accp[8][4]) {
#pragma unroll
  for (int r = 0; r < 8; r++)
#pragma unroll
    for (int c = 0; c < 4; c++) { accg[r][c] = 0.f; accp[r][c] = 0.f; }
#pragma unroll 2
  for (int k = 0; k < CDIM; k++) {
    float4 wg = *(const float4*)(Wg + k * CDIM + tx * 4);
    float4 wp = *(const float4*)(Wp + k * CDIM + tx * 4);
#pragma unroll
    for (int r = 0; r < 8; r++) {
      float av = As[(ty * 8 + r) * CDIM + k];   // smem broadcast
      accg[r][0] += av * wg.x; accg[r][1] += av * wg.y;
      accg[r][2] += av * wg.z; accg[r][3] += av * wg.w;
      accp[r][0] += av * wp.x; accp[r][1] += av * wp.y;
      accp[r][2] += av * wp.z; accp[r][3] += av * wp.w;
    }
  }
}

__device__ __forceinline__ void store_trans(float* __restrict__ dst, int c0, int n0,
                                            float accg[8][4], float accp[8][4],
                                            const float* mk) {
#pragma unroll
  for (int c = 0; c < 4; c++) {
    float v[8];
#pragma unroll
    for (int r = 0; r < 8; r++)
      v[r] = sigmoidf(accg[r][c]) * accp[r][c] * mk[r];
    *(float4*)(dst + (size_t)(c0 + c) * NROWS + n0)     = make_float4(v[0], v[1], v[2], v[3]);
    *(float4*)(dst + (size_t)(c0 + c) * NROWS + n0 + 4) = make_float4(v[4], v[5], v[6], v[7]);
  }
}

__global__ __launch_bounds__(256) void k_proj(
    const int* __restrict__ mask,
    const float* __restrict__ Wga, const float* __restrict__ Wpa,
    const float* __restrict__ Wgb, const float* __restrict__ Wpb,
    const float* __restrict__ Wgo) {
  __shared__ float As[64 * CDIM];   // 32 KB
  int t = threadIdx.x;
  int row0 = blockIdx.x * 64;
  {
    const float4* src = (const float4*)(d_zln + (size_t)row0 * CDIM);
    float4* dstp = (float4*)As;
#pragma unroll
    for (int q = 0; q < 8; q++) dstp[t + 256 * q] = src[t + 256 * q];
  }
  __syncthreads();
  int tx = t & 31, ty = t >> 5;
  float mk[8];
#pragma unroll
  for (int r = 0; r < 8; r++) mk[r] = (float)mask[row0 + ty * 8 + r];

  float accg[8][4], accp[8][4];
  // a = sigmoid(zln@Wga) * (zln@Wpa) * mask  -> channel-major
  gemm_pair(As, tx, ty, Wga, Wpa, accg, accp);
  store_trans(d_at, tx * 4, row0 + ty * 8, accg, accp, mk);
  // b
  gemm_pair(As, tx, ty, Wgb, Wpb, accg, accp);
  store_trans(d_bt, tx * 4, row0 + ty * 8, accg, accp, mk);
  // g = sigmoid(zln@Wgo), natural [n][c] layout
#pragma unroll
  for (int r = 0; r < 8; r++)
#pragma unroll
    for (int c = 0; c < 4; c++) accg[r][c] = 0.f;
#pragma unroll 2
  for (int k = 0; k < CDIM; k++) {
    float4 wg = *(const float4*)(Wgo + k * CDIM + tx * 4);
#pragma unroll
    for (int r = 0; r < 8; r++) {
      float av = As[(ty * 8 + r) * CDIM + k];
      accg[r][0] += av * wg.x; accg[r][1] += av * wg.y;
      accg[r][2] += av * wg.z; accg[r][3] += av * wg.w;
    }
  }
#pragma unroll
  for (int r = 0; r < 8; r++) {
    size_t n = (size_t)(row0 + ty * 8 + r);
    float4 o = make_float4(sigmoidf(accg[r][0]), sigmoidf(accg[r][1]),
                           sigmoidf(accg[r][2]), sigmoidf(accg[r][3]));
    *(float4*)(d_g + n * CDIM + tx * 4) = o;
  }
}

// ---------------- K2: channel-batched einsum m_c = A_c @ B_c^T -------------
// 64x64 output tile, k-chunks of 32, 16x16 thread grid, 4x4 per thread.
__global__ __launch_bounds__(256) void k_einsum() {
  __shared__ float As[32][68];
  __shared__ float Bs[32][68];
  int c = blockIdx.z;
  int i0 = blockIdx.x * 64, j0 = blockIdx.y * 64;
  const float* Ap = d_at + (size_t)c * NROWS;
  const float* Bp = d_bt + (size_t)c * NROWS;
  int t = threadIdx.x;
  int tx = t & 15, ty = t >> 4;
  int lk = t & 31, lwarp = t >> 5;
  float acc[4][4] = {};
  for (int kc = 0; kc < LDIM; kc += 32) {
#pragma unroll
    for (int q = 0; q < 8; q++) {
      int r = lwarp + q * 8;
      As[lk][r] = Ap[(size_t)(i0 + r) * LDIM + kc + lk];
      Bs[lk][r] = Bp[(size_t)(j0 + r) * LDIM + kc + lk];
    }
    __syncthreads();
#pragma unroll
    for (int kk = 0; kk < 32; kk++) {
      float4 af = *(const float4*)&As[kk][ty * 4];
      float4 bf = *(const float4*)&Bs[kk][tx * 4];
      acc[0][0] += af.x * bf.x; acc[0][1] += af.x * bf.y; acc[0][2] += af.x * bf.z; acc[0][3] += af.x * bf.w;
      acc[1][0] += af.y * bf.x; acc[1][1] += af.y * bf.y; acc[1][2] += af.y * bf.z; acc[1][3] += af.y * bf.w;
      acc[2][0] += af.z * bf.x; acc[2][1] += af.z * bf.y; acc[2][2] += af.z * bf.z; acc[2][3] += af.z * bf.w;
      acc[3][0] += af.w * bf.x; acc[3][1] += af.w * bf.y; acc[3][2] += af.w * bf.z; acc[3][3] += af.w * bf.w;
    }
    __syncthreads();
  }
#pragma unroll
  for (int rr = 0; rr < 4; rr++) {
    float4 v = make_float4(acc[rr][0], acc[rr][1], acc[rr][2], acc[rr][3]);
    *(float4*)(d_mt + (size_t)c * NROWS + (size_t)(i0 + ty * 4 + rr) * LDIM + j0 + tx * 4) = v;
  }
}

// ---------------- K3: LN(m) over c, @W_proj_out, * g * mask ----------------
// Block: one i, 32 j values.
__global__ __launch_bounds__(256) void k_out(
    const float* __restrict__ lnw, const float* __restrict__ lnb,
    const float* __restrict__ Wpo, const int* __restrict__ mask,
    float* __restrict__ out) {
  __shared__ float ms[CDIM][33];
  int i = blockIdx.y;
  int j0 = blockIdx.x * 32;
  int t = threadIdx.x;
  int lane = t & 31, warp = t >> 5;
  // gather m[c][i][j0+jj] (coalesced per channel)
#pragma unroll
  for (int q = 0; q < 16; q++) {
    int c = warp + 8 * q;
    ms[c][lane] = d_mt[(size_t)c * NROWS + (size_t)i * LDIM + j0 + lane];
  }
  __syncthreads();
  // layernorm over c: each warp owns 4 j-columns
  float w0 = lnw[lane], w1 = lnw[lane + 32], w2 = lnw[lane + 64], w3 = lnw[lane + 96];
  float b0 = lnb[lane], b1 = lnb[lane + 32], b2 = lnb[lane + 64], b3 = lnb[lane + 96];
#pragma unroll
  for (int s = 0; s < 4; s++) {
    int jj = warp * 4 + s;
    float x0 = ms[lane][jj], x1 = ms[lane + 32][jj];
    float x2 = ms[lane + 64][jj], x3 = ms[lane + 96][jj];
    float mu = warp_sum(x0 + x1 + x2 + x3) * (1.f / CDIM);
    float d0 = x0 - mu, d1 = x1 - mu, d2 = x2 - mu, d3 = x3 - mu;
    float var = warp_sum(d0 * d0 + d1 * d1 + d2 * d2 + d3 * d3) * (1.f / CDIM);
    float rstd = rsqrtf(var + EPSV);
    ms[lane][jj]      = d0 * rstd * w0 + b0;
    ms[lane + 32][jj] = d1 * rstd * w1 + b1;
    ms[lane + 64][jj] = d2 * rstd * w2 + b2;
    ms[lane + 96][jj] = d3 * rstd * w3 + b3;
  }
  __syncthreads();
  // matvec with W_proj_out; thread (tx=lane, ty=warp): cols 4*lane, jj = warp+8q
  float acc[4][4] = {};
  for (int cch = 0; cch < CDIM; cch++) {
    float4 w4 = *(const float4*)(Wpo + cch * CDIM + lane * 4);
#pragma unroll
    for (int q = 0; q < 4; q++) {
      float mv = ms[cch][warp + 8 * q];
      acc[q][0] += mv * w4.x; acc[q][1] += mv * w4.y;
      acc[q][2] += mv * w4.z; acc[q][3] += mv * w4.w;
    }
  }
#pragma unroll
  for (int q = 0; q < 4; q++) {
    int j = j0 + warp + 8 * q;
    size_t n = (size_t)i * LDIM + j;
    float mkv = (float)mask[n];
    float4 g4 = *(const float4*)(d_g + n * CDIM + lane * 4);
    float4 o = make_float4(g4.x * acc[q][0] * mkv, g4.y * acc[q][1] * mkv,
                           g4.z * acc[q][2] * mkv, g4.w * acc[q][3] * mkv);
    *(float4*)(out + n * CDIM + lane * 4) = o;
  }
}

// ---------------- launch ----------------------------------------------------
extern "C" void kernel_launch(void* const* d_in, const int* in_sizes, int n_in,
                              void* d_out, int out_size) {
  const float* z       = (const float*)d_in[0];
  const int*   mask    = (const int*)  d_in[1];
  const float* ln_in_w = (const float*)d_in[2];
  const float* ln_in_b = (const float*)d_in[3];
  const float* ln_out_w = (const float*)d_in[4];
  const float* ln_out_b = (const float*)d_in[5];
  const float* Wpa = (const float*)d_in[6];
  const float* Wga = (const float*)d_in[7];
  const float* Wpb = (const float*)d_in[8];
  const float* Wgb = (const float*)d_in[9];
  const float* Wgo = (const float*)d_in[10];
  const float* Wpo = (const float*)d_in[11];
  float* out = (float*)d_out;

  k_ln_in<<<NROWS / 8, 256>>>(z, ln_in_w, ln_in_b);
  k_proj<<<NROWS / 64, 256>>>(mask, Wga, Wpa, Wgb, Wpb, Wgo);
  dim3 g2(LDIM / 64, LDIM / 64, CDIM);
  k_einsum<<<g2, 256>>>();
  dim3 g3(LDIM / 32, LDIM);
  k_out<<<g3, 256>>>(ln_out_w, ln_out_b, Wpo, mask, out);
}

// round 3
// speedup vs baseline: 1.2720x; 1.2720x over previous
#include <cuda_runtime.h>
#include <cuda_bf16.h>
#include <cstdint>

#define LDIM 512
#define CDIM 128
#define NROWS (LDIM * LDIM)   // 262144 pair rows
#define EPSV 1e-5f

// ---------------- scratch (static device memory; no runtime allocation) ----
__device__ float d_zln[(size_t)NROWS * CDIM];          // layernormed z, [n][c]
__device__ float d_g  [(size_t)NROWS * CDIM];          // sigmoid(zln @ W_gate_out), [n][c]
__device__ __nv_bfloat16 d_a_hi[(size_t)CDIM * NROWS]; // a split: [c][i][k]
__device__ __nv_bfloat16 d_a_lo[(size_t)CDIM * NROWS];
__device__ __nv_bfloat16 d_b_hi[(size_t)CDIM * NROWS]; // b split: [c][j][k]
__device__ __nv_bfloat16 d_b_lo[(size_t)CDIM * NROWS];
__device__ float d_mt [(size_t)CDIM * NROWS];          // einsum result: [c][i][j]

// ---------------- arch-generic PTX helpers (plain sm_103 target!) ----------
__device__ __forceinline__ uint32_t smem_u32(const void* p) {
  uint32_t a;
  asm("{ .reg .u64 t; cvta.to.shared.u64 t, %1; cvt.u32.u64 %0, t; }" : "=r"(a) : "l"(p));
  return a;
}
#define CP_ASYNC16(s, g) \
  asm volatile("cp.async.cg.shared.global [%0], [%1], 16;" :: "r"(s), "l"(g) : "memory")
#define CP_COMMIT() asm volatile("cp.async.commit_group;" ::: "memory")
#define CP_WAIT(n)  asm volatile("cp.async.wait_group %0;" :: "n"(n) : "memory")

#define LDSM_X4(r0, r1, r2, r3, addr) \
  asm volatile("ldmatrix.sync.aligned.m8n8.x4.shared.b16 {%0,%1,%2,%3}, [%4];" \
    : "=r"(r0), "=r"(r1), "=r"(r2), "=r"(r3) : "r"(addr))

#define MMA16816(d, a, b0, b1) \
  asm volatile("mma.sync.aligned.m16n8k16.row.col.f32.bf16.bf16.f32 " \
    "{%0,%1,%2,%3}, {%4,%5,%6,%7}, {%8,%9}, {%0,%1,%2,%3};" \
    : "+f"((d)[0]), "+f"((d)[1]), "+f"((d)[2]), "+f"((d)[3]) \
    : "r"((a)[0]), "r"((a)[1]), "r"((a)[2]), "r"((a)[3]), "r"(b0), "r"(b1))

__device__ __forceinline__ float warp_sum(float v) {
#pragma unroll
  for (int o = 16; o > 0; o >>= 1) v += __shfl_xor_sync(0xffffffffu, v, o);
  return v;
}
__device__ __forceinline__ float sigmoidf(float x) {
  return 1.f / (1.f + __expf(-x));
}
__device__ __forceinline__ unsigned pack2(float a, float b) {
  __nv_bfloat162 t = __floats2bfloat162_rn(a, b);
  return *(unsigned*)&t;
}

// ---------------- K0: LayerNorm of z over channel dim ----------------------
__global__ __launch_bounds__(256) void k_ln_in(const float* __restrict__ z,
                                               const float* __restrict__ w,
                                               const float* __restrict__ b) {
  int warp = threadIdx.x >> 5, lane = threadIdx.x & 31;
  size_t row = (size_t)blockIdx.x * 8 + warp;
  const float4 v = *(const float4*)(z + row * CDIM + lane * 4);
  float mu = warp_sum(v.x + v.y + v.z + v.w) * (1.f / CDIM);
  float dx = v.x - mu, dy = v.y - mu, dz = v.z - mu, dw = v.w - mu;
  float var = warp_sum(dx * dx + dy * dy + dz * dz + dw * dw) * (1.f / CDIM);
  float rstd = rsqrtf(var + EPSV);
  float4 wv = *(const float4*)(w + lane * 4);
  float4 bv = *(const float4*)(b + lane * 4);
  float4 o = make_float4(dx * rstd * wv.x + bv.x, dy * rstd * wv.y + bv.y,
                         dz * rstd * wv.z + bv.z, dw * rstd * wv.w + bv.w);
  *(float4*)(d_zln + row * CDIM + lane * 4) = o;
}

// ---------------- K1: projections + gates (FFMA fp32, unchanged) -----------
__device__ __forceinline__ void gemm_pair(const float* __restrict__ As, int tx, int ty,
                                          const float* __restrict__ Wg,
                                          const float* __restrict__ Wp,
                                          float accg[8][4], float accp[8][4]) {
#pragma unroll
  for (int r = 0; r < 8; r++)
#pragma unroll
    for (int c = 0; c < 4; c++) { accg[r][c] = 0.f; accp[r][c] = 0.f; }
#pragma unroll 2
  for (int k = 0; k < CDIM; k++) {
    float4 wg = *(const float4*)(Wg + k * CDIM + tx * 4);
    float4 wp = *(const float4*)(Wp + k * CDIM + tx * 4);
#pragma unroll
    for (int r = 0; r < 8; r++) {
      float av = As[(ty * 8 + r) * CDIM + k];
      accg[r][0] += av * wg.x; accg[r][1] += av * wg.y;
      accg[r][2] += av * wg.z; accg[r][3] += av * wg.w;
      accp[r][0] += av * wp.x; accp[r][1] += av * wp.y;
      accp[r][2] += av * wp.z; accp[r][3] += av * wp.w;
    }
  }
}

__device__ __forceinline__ void store_trans_split(
    __nv_bfloat16* __restrict__ dhi, __nv_bfloat16* __restrict__ dlo,
    int c0, int n0, float accg[8][4], float accp[8][4], const float* mk) {
#pragma unroll
  for (int c = 0; c < 4; c++) {
    float hi[8], lo[8];
#pragma unroll
    for (int r = 0; r < 8; r++) {
      float v = sigmoidf(accg[r][c]) * accp[r][c] * mk[r];
      hi[r] = __bfloat162float(__float2bfloat16(v));
      lo[r] = v - hi[r];
    }
    size_t base = (size_t)(c0 + c) * NROWS + n0;
    uint4 uh, ul;
    uh.x = pack2(hi[0], hi[1]); uh.y = pack2(hi[2], hi[3]);
    uh.z = pack2(hi[4], hi[5]); uh.w = pack2(hi[6], hi[7]);
    ul.x = pack2(lo[0], lo[1]); ul.y = pack2(lo[2], lo[3]);
    ul.z = pack2(lo[4], lo[5]); ul.w = pack2(lo[6], lo[7]);
    *(uint4*)(dhi + base) = uh;
    *(uint4*)(dlo + base) = ul;
  }
}

__global__ __launch_bounds__(256) void k_proj(
    const int* __restrict__ mask,
    const float* __restrict__ Wga, const float* __restrict__ Wpa,
    const float* __restrict__ Wgb, const float* __restrict__ Wpb,
    const float* __restrict__ Wgo) {
  __shared__ float As[64 * CDIM];   // 32 KB
  int t = threadIdx.x;
  int row0 = blockIdx.x * 64;
  {
    const float4* src = (const float4*)(d_zln + (size_t)row0 * CDIM);
    float4* dstp = (float4*)As;
#pragma unroll
    for (int q = 0; q < 8; q++) dstp[t + 256 * q] = src[t + 256 * q];
  }
  __syncthreads();
  int tx = t & 31, ty = t >> 5;
  float mk[8];
#pragma unroll
  for (int r = 0; r < 8; r++) mk[r] = (float)mask[row0 + ty * 8 + r];

  float accg[8][4], accp[8][4];
  gemm_pair(As, tx, ty, Wga, Wpa, accg, accp);
  store_trans_split(d_a_hi, d_a_lo, tx * 4, row0 + ty * 8, accg, accp, mk);
  gemm_pair(As, tx, ty, Wgb, Wpb, accg, accp);
  store_trans_split(d_b_hi, d_b_lo, tx * 4, row0 + ty * 8, accg, accp, mk);
#pragma unroll
  for (int r = 0; r < 8; r++)
#pragma unroll
    for (int c = 0; c < 4; c++) accg[r][c] = 0.f;
#pragma unroll 2
  for (int k = 0; k < CDIM; k++) {
    float4 wg = *(const float4*)(Wgo + k * CDIM + tx * 4);
#pragma unroll
    for (int r = 0; r < 8; r++) {
      float av = As[(ty * 8 + r) * CDIM + k];
      accg[r][0] += av * wg.x; accg[r][1] += av * wg.y;
      accg[r][2] += av * wg.z; accg[r][3] += av * wg.w;
    }
  }
#pragma unroll
  for (int r = 0; r < 8; r++) {
    size_t n = (size_t)(row0 + ty * 8 + r);
    float4 o = make_float4(sigmoidf(accg[r][0]), sigmoidf(accg[r][1]),
                           sigmoidf(accg[r][2]), sigmoidf(accg[r][3]));
    *(float4*)(d_g + n * CDIM + tx * 4) = o;
  }
}

// ---------------- K2: channel-batched einsum on HMMA (mma.sync) ------------
// Per CTA: one channel c, 128x128 (i,j) output tile. 8 warps in 2(M)x4(N),
// warp tile 64x32, mma.m16n8k16 bf16. 3-term hi/lo split accumulated into the
// same fp32 accumulators; one smem load (A_hi,A_lo,B_hi,B_lo) serves all 3.
// K chunks of 32, cp.async double-buffered. smem row stride 40 elems (80B):
// ldmatrix conflict-free (row*5 mod 8 is a permutation).
#define EROWB 80          // smem bytes per row (32 bf16 + 8 pad)
#define ARRB (128 * EROWB)      // 10240 B per array
#define BUFB (4 * ARRB)         // 40960 B per stage
#define EIN_SMEM (2 * BUFB)     // 81920 B

__global__ __launch_bounds__(256) void k_einsum_mma() {
  extern __shared__ char smem[];
  const uint32_t sbase = smem_u32(smem);
  const int c = blockIdx.z;
  const int i0 = blockIdx.x * 128, j0 = blockIdx.y * 128;
  const int tid = threadIdx.x;
  const size_t coff = (size_t)c * NROWS;

  // global base pointers for the 4 staged arrays (rows: A from a@i0, B from b@j0)
  const __nv_bfloat16* gsrc[4] = {
      d_a_hi + coff + (size_t)i0 * LDIM, d_a_lo + coff + (size_t)i0 * LDIM,
      d_b_hi + coff + (size_t)j0 * LDIM, d_b_lo + coff + (size_t)j0 * LDIM};

  const int larr = tid >> 6;          // which array this thread loads
  const int lrow = (tid & 63) * 2;    // 2 rows per thread
  const __nv_bfloat16* lsrc = gsrc[larr];
  const uint32_t lsmem = sbase + larr * ARRB + lrow * EROWB;

#define ISSUE_LOAD(buf, kc) do { \
    const char* g0 = (const char*)(lsrc + (size_t)lrow * LDIM + (kc)); \
    const char* g1 = (const char*)(lsrc + (size_t)(lrow + 1) * LDIM + (kc)); \
    uint32_t s0 = lsmem + (buf) * BUFB; \
    uint32_t s1 = s0 + EROWB; \
    CP_ASYNC16(s0,      g0);      CP_ASYNC16(s0 + 16, g0 + 16); \
    CP_ASYNC16(s0 + 32, g0 + 32); CP_ASYNC16(s0 + 48, g0 + 48); \
    CP_ASYNC16(s1,      g1);      CP_ASYNC16(s1 + 16, g1 + 16); \
    CP_ASYNC16(s1 + 32, g1 + 32); CP_ASYNC16(s1 + 48, g1 + 48); \
    CP_COMMIT(); \
  } while (0)

  const int w = tid >> 5, l = tid & 31;
  const int wm = w & 1, wn = w >> 1;          // 2 x 4 warp grid
  // ldmatrix per-lane row/col offsets
  const int a_r = l & 15, a_c = l >> 4;                 // A tiles m16k16
  const int b_r = (l & 7) + ((l >> 4) << 3);            // B tile-pairs (two n8k16)
  const int b_c = (l >> 3) & 1;

  float acc[4][4][4];
#pragma unroll
  for (int mt = 0; mt < 4; mt++)
#pragma unroll
    for (int nt = 0; nt < 4; nt++)
#pragma unroll
      for (int q = 0; q < 4; q++) acc[mt][nt][q] = 0.f;

  ISSUE_LOAD(0, 0);

  for (int ci = 0; ci < 16; ci++) {
    const int buf = ci & 1;
    if (ci < 15) ISSUE_LOAD(buf ^ 1, (ci + 1) * 32);
    if (ci < 15) { CP_WAIT(1); } else { CP_WAIT(0); }
    __syncthreads();

    const uint32_t bufbase = sbase + buf * BUFB;
#pragma unroll
    for (int term = 0; term < 3; term++) {
      const uint32_t Ab = bufbase + (term == 1 ? ARRB : 0);               // A_hi or A_lo
      const uint32_t Bb = bufbase + 2 * ARRB + (term == 2 ? ARRB : 0);    // B_hi or B_lo
#pragma unroll
      for (int ks = 0; ks < 2; ks++) {
        uint32_t af[4][4], bf[2][4];
#pragma unroll
        for (int mt = 0; mt < 4; mt++) {
          uint32_t addr = Ab + (uint32_t)(wm * 64 + mt * 16 + a_r) * EROWB + ks * 32 + a_c * 16;
          LDSM_X4(af[mt][0], af[mt][1], af[mt][2], af[mt][3], addr);
        }
#pragma unroll
        for (int np = 0; np < 2; np++) {
          uint32_t addr = Bb + (uint32_t)(wn * 32 + np * 16 + b_r) * EROWB + ks * 32 + b_c * 16;
          LDSM_X4(bf[np][0], bf[np][1], bf[np][2], bf[np][3], addr);
        }
#pragma unroll
        for (int mt = 0; mt < 4; mt++) {
#pragma unroll
          for (int nt = 0; nt < 4; nt++) {
            uint32_t b0 = (nt & 1) ? bf[nt >> 1][2] : bf[nt >> 1][0];
            uint32_t b1 = (nt & 1) ? bf[nt >> 1][3] : bf[nt >> 1][1];
            MMA16816(acc[mt][nt], af[mt], b0, b1);
          }
        }
      }
    }
    __syncthreads();
  }

  // epilogue: d_mt[c][i][j]; acc thread map: rows (l>>2)+{0,8}, cols 2*(l&3)+{0,1}
  float* mbase = d_mt + coff;
#pragma unroll
  for (int mt = 0; mt < 4; mt++) {
#pragma unroll
    for (int h = 0; h < 2; h++) {
      int row = i0 + wm * 64 + mt * 16 + (l >> 2) + h * 8;
      float* rp = mbase + (size_t)row * LDIM + j0 + wn * 32 + (l & 3) * 2;
#pragma unroll
      for (int nt = 0; nt < 4; nt++) {
        float2 v = make_float2(acc[mt][nt][h * 2], acc[mt][nt][h * 2 + 1]);
        *(float2*)(rp + nt * 8) = v;
      }
    }
  }
#undef ISSUE_LOAD
}

// ---------------- K3: LN(m) over c, @W_proj_out, * g * mask ----------------
__global__ __launch_bounds__(256) void k_out(
    const float* __restrict__ lnw, const float* __restrict__ lnb,
    const float* __restrict__ Wpo, const int* __restrict__ mask,
    float* __restrict__ out) {
  __shared__ float ms[CDIM][33];
  int i = blockIdx.y;
  int j0 = blockIdx.x * 32;
  int t = threadIdx.x;
  int lane = t & 31, warp = t >> 5;
#pragma unroll
  for (int q = 0; q < 16; q++) {
    int c = warp + 8 * q;
    ms[c][lane] = d_mt[(size_t)c * NROWS + (size_t)i * LDIM + j0 + lane];
  }
  __syncthreads();
  float w0 = lnw[lane], w1 = lnw[lane + 32], w2 = lnw[lane + 64], w3 = lnw[lane + 96];
  float b0 = lnb[lane], b1 = lnb[lane + 32], b2 = lnb[lane + 64], b3 = lnb[lane + 96];
#pragma unroll
  for (int s = 0; s < 4; s++) {
    int jj = warp * 4 + s;
    float x0 = ms[lane][jj], x1 = ms[lane + 32][jj];
    float x2 = ms[lane + 64][jj], x3 = ms[lane + 96][jj];
    float mu = warp_sum(x0 + x1 + x2 + x3) * (1.f / CDIM);
    float d0 = x0 - mu, d1 = x1 - mu, d2 = x2 - mu, d3 = x3 - mu;
    float var = warp_sum(d0 * d0 + d1 * d1 + d2 * d2 + d3 * d3) * (1.f / CDIM);
    float rstd = rsqrtf(var + EPSV);
    ms[lane][jj]      = d0 * rstd * w0 + b0;
    ms[lane + 32][jj] = d1 * rstd * w1 + b1;
    ms[lane + 64][jj] = d2 * rstd * w2 + b2;
    ms[lane + 96][jj] = d3 * rstd * w3 + b3;
  }
  __syncthreads();
  float acc[4][4] = {};
  for (int cch = 0; cch < CDIM; cch++) {
    float4 w4 = *(const float4*)(Wpo + cch * CDIM + lane * 4);
#pragma unroll
    for (int q = 0; q < 4; q++) {
      float mv = ms[cch][warp + 8 * q];
      acc[q][0] += mv * w4.x; acc[q][1] += mv * w4.y;
      acc[q][2] += mv * w4.z; acc[q][3] += mv * w4.w;
    }
  }
#pragma unroll
  for (int q = 0; q < 4; q++) {
    int j = j0 + warp + 8 * q;
    size_t n = (size_t)i * LDIM + j;
    float mkv = (float)mask[n];
    float4 g4 = *(const float4*)(d_g + n * CDIM + lane * 4);
    float4 o = make_float4(g4.x * acc[q][0] * mkv, g4.y * acc[q][1] * mkv,
                           g4.z * acc[q][2] * mkv, g4.w * acc[q][3] * mkv);
    *(float4*)(out + n * CDIM + lane * 4) = o;
  }
}

// ---------------- launch ----------------------------------------------------
extern "C" void kernel_launch(void* const* d_in, const int* in_sizes, int n_in,
                              void* d_out, int out_size) {
  const float* z        = (const float*)d_in[0];
  const int*   mask     = (const int*)  d_in[1];
  const float* ln_in_w  = (const float*)d_in[2];
  const float* ln_in_b  = (const float*)d_in[3];
  const float* ln_out_w = (const float*)d_in[4];
  const float* ln_out_b = (const float*)d_in[5];
  const float* Wpa = (const float*)d_in[6];
  const float* Wga = (const float*)d_in[7];
  const float* Wpb = (const float*)d_in[8];
  const float* Wgb = (const float*)d_in[9];
  const float* Wgo = (const float*)d_in[10];
  const float* Wpo = (const float*)d_in[11];
  float* out = (float*)d_out;

  cudaFuncSetAttribute(k_einsum_mma, cudaFuncAttributeMaxDynamicSharedMemorySize, EIN_SMEM);

  k_ln_in<<<NROWS / 8, 256>>>(z, ln_in_w, ln_in_b);
  k_proj<<<NROWS / 64, 256>>>(mask, Wga, Wpa, Wgb, Wpb, Wgo);
  dim3 g2(LDIM / 128, LDIM / 128, CDIM);
  k_einsum_mma<<<g2, 256, EIN_SMEM>>>();
  dim3 g3(LDIM / 32, LDIM);
  k_out<<<g3, 256>>>(ln_out_w, ln_out_b, Wpo, mask, out);
}

// round 4
// speedup vs baseline: 1.7470x; 1.3734x over previous
#include <cuda_runtime.h>
#include <cuda_bf16.h>
#include <cstdint>

#define LDIM 512
#define CDIM 128
#define NROWS (LDIM * LDIM)   // 262144 pair rows
#define EPSV 1e-5f

// ---------------- scratch (static device memory; no runtime allocation) ----
__device__ float d_g  [(size_t)NROWS * CDIM];          // sigmoid(zln @ W_gate_out), [n][c]
__device__ __nv_bfloat16 d_a_hi[(size_t)CDIM * NROWS]; // a split: [c][i][k]
__device__ __nv_bfloat16 d_a_lo[(size_t)CDIM * NROWS];
__device__ __nv_bfloat16 d_b_hi[(size_t)CDIM * NROWS]; // b split: [c][j][k]
__device__ __nv_bfloat16 d_b_lo[(size_t)CDIM * NROWS];
__device__ float d_mt [(size_t)CDIM * NROWS];          // einsum result: [c][i][j]
// pre-transposed, pre-swizzled weights [w][ch][k] bf16 hi/lo (B operand layout)
__device__ __nv_bfloat16 d_w_hi[5 * CDIM * CDIM];
__device__ __nv_bfloat16 d_w_lo[5 * CDIM * CDIM];

// ---------------- arch-generic PTX helpers (plain sm_103 target!) ----------
__device__ __forceinline__ uint32_t smem_u32(const void* p) {
  uint32_t a;
  asm("{ .reg .u64 t; cvta.to.shared.u64 t, %1; cvt.u32.u64 %0, t; }" : "=r"(a) : "l"(p));
  return a;
}
#define CP_ASYNC16(s, g) \
  asm volatile("cp.async.cg.shared.global [%0], [%1], 16;" :: "r"(s), "l"(g) : "memory")
#define CP_COMMIT() asm volatile("cp.async.commit_group;" ::: "memory")
#define CP_WAIT(n)  asm volatile("cp.async.wait_group %0;" :: "n"(n) : "memory")

#define LDSM_X4(r0, r1, r2, r3, addr) \
  asm volatile("ldmatrix.sync.aligned.m8n8.x4.shared.b16 {%0,%1,%2,%3}, [%4];" \
    : "=r"(r0), "=r"(r1), "=r"(r2), "=r"(r3) : "r"(addr))

#define MMA16816(d, a, b0, b1) \
  asm volatile("mma.sync.aligned.m16n8k16.row.col.f32.bf16.bf16.f32 " \
    "{%0,%1,%2,%3}, {%4,%5,%6,%7}, {%8,%9}, {%0,%1,%2,%3};" \
    : "+f"((d)[0]), "+f"((d)[1]), "+f"((d)[2]), "+f"((d)[3]) \
    : "r"((a)[0]), "r"((a)[1]), "r"((a)[2]), "r"((a)[3]), "r"(b0), "r"(b1))

#define MOVMAT(d, s) \
  asm volatile("movmatrix.sync.aligned.m8n8.trans.b16 %0, %1;" : "=r"(d) : "r"(s))

__device__ __forceinline__ float warp_sum(float v) {
#pragma unroll
  for (int o = 16; o > 0; o >>= 1) v += __shfl_xor_sync(0xffffffffu, v, o);
  return v;
}
__device__ __forceinline__ float sigmoidf(float x) {
  return 1.f / (1.f + __expf(-x));
}
__device__ __forceinline__ unsigned pack2(float a, float b) {
  __nv_bfloat162 t = __floats2bfloat162_rn(a, b);
  return *(unsigned*)&t;
}

// ---------------- K_prew: W -> [ch][k] bf16 hi/lo, swizzle baked ------------
// out[w][ch][k'] = split(W[k][ch]);  k' chunk16 index = (k>>3) ^ (ch&7)
__global__ __launch_bounds__(256) void k_prew(
    const float* __restrict__ Wga, const float* __restrict__ Wpa,
    const float* __restrict__ Wgb, const float* __restrict__ Wpb,
    const float* __restrict__ Wgo) {
  const float* srcs[5] = {Wga, Wpa, Wgb, Wpb, Wgo};
  const float* W = srcs[blockIdx.y];
  int t = threadIdx.x;
  int ch = blockIdx.x * 16 + (t >> 4);
  int k0 = (t & 15) * 8;
  uint32_t hr[4], lr[4];
#pragma unroll
  for (int q = 0; q < 4; q++) {
    float v0 = W[(k0 + 2 * q) * CDIM + ch];
    float v1 = W[(k0 + 2 * q + 1) * CDIM + ch];
    float h0 = __bfloat162float(__float2bfloat16(v0));
    float h1 = __bfloat162float(__float2bfloat16(v1));
    hr[q] = pack2(h0, h1);
    lr[q] = pack2(v0 - h0, v1 - h1);
  }
  size_t off = (size_t)blockIdx.y * (CDIM * CDIM) + (size_t)ch * CDIM +
               (((k0 >> 3) ^ (ch & 7)) * 8);
  *(uint4*)(d_w_hi + off) = make_uint4(hr[0], hr[1], hr[2], hr[3]);
  *(uint4*)(d_w_lo + off) = make_uint4(lr[0], lr[1], lr[2], lr[3]);
}

// ---------------- K1: fused LN + 5-way projection on HMMA -------------------
// CTA: 128 pair rows. A (zln) hi/lo in smem, K=128 resident, XOR-swizzled.
// W staged via cp.async from d_w_* in K-halves, double buffered.
// Stages: 0 = (Wga,Wpa)->a, 1 = (Wgb,Wpb)->b, 2 = Wgo->g.
#define APITCH 256
#define SA_BYTES (128 * APITCH)     // 32 KB per A array
#define WPITCH 128
#define SW_ARR (128 * WPITCH)       // 16 KB per W array (one K-half)
#define SW_BUF (4 * SW_ARR)         // 64 KB per buffer
#define PROJ_SMEM (2 * SA_BYTES + 2 * SW_BUF)   // 196608 B

__device__ __forceinline__ void proj_issue_chunk(int q, int t, uint32_t sW) {
  int s = q >> 1, half = q & 1;
  int arr = t >> 6;          // 0..3 -> {g_hi, g_lo, p_hi, p_lo}
  int ch = (t & 63) * 2;
  if (s < 2 || arr < 2) {    // stage 2 has only the gate weight
    int widx = s * 2 + (arr >> 1);
    const __nv_bfloat16* base = (arr & 1) ? d_w_lo : d_w_hi;
    const __nv_bfloat16* src = base + (size_t)widx * (CDIM * CDIM) + (size_t)ch * CDIM + half * 64;
    uint32_t dst = sW + (q & 1) * SW_BUF + arr * SW_ARR + ch * WPITCH;
#pragma unroll
    for (int rr = 0; rr < 2; rr++) {
      const char* g = (const char*)(src + rr * CDIM);
      uint32_t d = dst + rr * WPITCH;
#pragma unroll
      for (int cc = 0; cc < 8; cc++) CP_ASYNC16(d + cc * 16, g + cc * 16);
    }
  }
  CP_COMMIT();
}

__global__ __launch_bounds__(256) void k_projmma(
    const float* __restrict__ z, const int* __restrict__ mask,
    const float* __restrict__ lnw, const float* __restrict__ lnb) {
  extern __shared__ char smem[];
  const uint32_t sbase = smem_u32(smem);
  const uint32_t sAhi = sbase, sW = sbase + 2 * SA_BYTES;
  const int n0 = blockIdx.x * 128;
  const int t = threadIdx.x, l = t & 31, w = t >> 5;

  // prefetch first two W chunks, overlapped with LN
  proj_issue_chunk(0, t, sW);
  proj_issue_chunk(1, t, sW);

  // ---- LN: warp handles rows w, w+8, ..., writes A hi/lo into smem --------
  {
    float4 wv = *(const float4*)(lnw + l * 4);
    float4 bv = *(const float4*)(lnb + l * 4);
#pragma unroll 4
    for (int it = 0; it < 16; it++) {
      int r = w + it * 8;
      float4 v = *(const float4*)(z + (size_t)(n0 + r) * CDIM + l * 4);
      float mu = warp_sum(v.x + v.y + v.z + v.w) * (1.f / CDIM);
      float dx = v.x - mu, dy = v.y - mu, dz = v.z - mu, dw = v.w - mu;
      float var = warp_sum(dx * dx + dy * dy + dz * dz + dw * dw) * (1.f / CDIM);
      float rstd = rsqrtf(var + EPSV);
      float o0 = dx * rstd * wv.x + bv.x, o1 = dy * rstd * wv.y + bv.y;
      float o2 = dz * rstd * wv.z + bv.z, o3 = dw * rstd * wv.w + bv.w;
      float h0 = __bfloat162float(__float2bfloat16(o0));
      float h1 = __bfloat162float(__float2bfloat16(o1));
      float h2 = __bfloat162float(__float2bfloat16(o2));
      float h3 = __bfloat162float(__float2bfloat16(o3));
      uint32_t off = r * APITCH + (((l >> 1) ^ (r & 7)) * 16) + (l & 1) * 8;
      *(uint2*)(smem + off) = make_uint2(pack2(h0, h1), pack2(h2, h3));
      *(uint2*)(smem + SA_BYTES + off) =
          make_uint2(pack2(o0 - h0, o1 - h1), pack2(o2 - h2, o3 - h3));
    }
  }
  __syncthreads();

  // ---- MMA mainloop --------------------------------------------------------
  const int a_r = l & 15, a_c = l >> 4;
  const int b_r = (l & 7) + ((l >> 4) << 3), b_c = (l >> 3) & 1;
  const int wm = w & 1, wn = w >> 1;   // 2(M) x 4(N) warps

  float mk[4][2];
#pragma unroll
  for (int mt = 0; mt < 4; mt++)
#pragma unroll
    for (int h = 0; h < 2; h++)
      mk[mt][h] = (float)mask[n0 + wm * 64 + mt * 16 + (l >> 2) + 8 * h];

  float accg[4][4][4], accp[4][4][4];

  for (int q = 0; q < 6; q++) {
    const int s = q >> 1, half = q & 1;
    if (half == 0) {
#pragma unroll
      for (int mt = 0; mt < 4; mt++)
#pragma unroll
        for (int nt = 0; nt < 4; nt++)
#pragma unroll
          for (int e = 0; e < 4; e++) { accg[mt][nt][e] = 0.f; accp[mt][nt][e] = 0.f; }
    }
    if (q < 5) { CP_WAIT(1); } else { CP_WAIT(0); }
    __syncthreads();

    const uint32_t wb = sW + (q & 1) * SW_BUF;
#pragma unroll
    for (int ks = 0; ks < 4; ks++) {
      const int kk = half * 4 + ks;
      uint32_t ah[4][4], al[4][4];
#pragma unroll
      for (int mt = 0; mt < 4; mt++) {
        int row = wm * 64 + mt * 16 + a_r;
        uint32_t addr = sAhi + row * APITCH + (((kk * 2 + a_c) ^ (row & 7)) * 16);
        LDSM_X4(ah[mt][0], ah[mt][1], ah[mt][2], ah[mt][3], addr);
        LDSM_X4(al[mt][0], al[mt][1], al[mt][2], al[mt][3], addr + SA_BYTES);
      }
#pragma unroll
      for (int gm = 0; gm < 2; gm++) {
        if (s == 2 && gm == 1) break;
        uint32_t bh[2][4], bl[2][4];
        const uint32_t Bh = wb + (gm * 2) * SW_ARR, Bl = Bh + SW_ARR;
#pragma unroll
        for (int np = 0; np < 2; np++) {
          int row = wn * 32 + np * 16 + b_r;
          uint32_t caddr = row * WPITCH + (((ks * 2 + b_c) ^ (row & 7)) * 16);
          LDSM_X4(bh[np][0], bh[np][1], bh[np][2], bh[np][3], Bh + caddr);
          LDSM_X4(bl[np][0], bl[np][1], bl[np][2], bl[np][3], Bl + caddr);
        }
#pragma unroll
        for (int mt = 0; mt < 4; mt++) {
#pragma unroll
          for (int nt = 0; nt < 4; nt++) {
            uint32_t h0 = (nt & 1) ? bh[nt >> 1][2] : bh[nt >> 1][0];
            uint32_t h1 = (nt & 1) ? bh[nt >> 1][3] : bh[nt >> 1][1];
            uint32_t l0 = (nt & 1) ? bl[nt >> 1][2] : bl[nt >> 1][0];
            uint32_t l1 = (nt & 1) ? bl[nt >> 1][3] : bl[nt >> 1][1];
            float* acc = gm ? accp[mt][nt] : accg[mt][nt];
            MMA16816(acc, ah[mt], h0, h1);
            MMA16816(acc, al[mt], h0, h1);
            MMA16816(acc, ah[mt], l0, l1);
          }
        }
      }
    }

    if (half == 1) {      // stage epilogue
      if (s < 2) {
        __nv_bfloat16* dhi = s ? d_b_hi : d_a_hi;
        __nv_bfloat16* dlo = s ? d_b_lo : d_a_lo;
#pragma unroll
        for (int mt = 0; mt < 4; mt++) {
#pragma unroll
          for (int h = 0; h < 2; h++) {
            int nb = n0 + wm * 64 + mt * 16 + 8 * h + 2 * (l & 3);
#pragma unroll
            for (int nt = 0; nt < 4; nt++) {
              float v0 = sigmoidf(accg[mt][nt][2 * h]) * accp[mt][nt][2 * h] * mk[mt][h];
              float v1 = sigmoidf(accg[mt][nt][2 * h + 1]) * accp[mt][nt][2 * h + 1] * mk[mt][h];
              float h0 = __bfloat162float(__float2bfloat16(v0));
              float h1 = __bfloat162float(__float2bfloat16(v1));
              uint32_t hreg = pack2(h0, h1), lreg = pack2(v0 - h0, v1 - h1);
              uint32_t ht, lt;
              MOVMAT(ht, hreg);
              MOVMAT(lt, lreg);
              size_t chrow = (size_t)(wn * 32 + nt * 8 + (l >> 2));
              *(uint32_t*)(dhi + chrow * NROWS + nb) = ht;
              *(uint32_t*)(dlo + chrow * NROWS + nb) = lt;
            }
          }
        }
      } else {            // g = sigmoid(zln @ Wgo), natural [n][c] layout
#pragma unroll
        for (int mt = 0; mt < 4; mt++) {
#pragma unroll
          for (int h = 0; h < 2; h++) {
            int n = n0 + wm * 64 + mt * 16 + (l >> 2) + 8 * h;
            float* dst = d_g + (size_t)n * CDIM + wn * 32 + 2 * (l & 3);
#pragma unroll
            for (int nt = 0; nt < 4; nt++) {
              float2 o = make_float2(sigmoidf(accg[mt][nt][2 * h]),
                                     sigmoidf(accg[mt][nt][2 * h + 1]));
              *(float2*)(dst + nt * 8) = o;
            }
          }
        }
      }
    }
    __syncthreads();
    if (q + 2 < 6) proj_issue_chunk(q + 2, t, sW);
  }
}

// ---------------- K2: channel-batched einsum on HMMA (unchanged) ------------
#define EROWB 80
#define ARRB (128 * EROWB)
#define BUFB (4 * ARRB)
#define EIN_SMEM (2 * BUFB)

__global__ __launch_bounds__(256) void k_einsum_mma() {
  extern __shared__ char smem[];
  const uint32_t sbase = smem_u32(smem);
  const int c = blockIdx.z;
  const int i0 = blockIdx.x * 128, j0 = blockIdx.y * 128;
  const int tid = threadIdx.x;
  const size_t coff = (size_t)c * NROWS;

  const __nv_bfloat16* gsrc[4] = {
      d_a_hi + coff + (size_t)i0 * LDIM, d_a_lo + coff + (size_t)i0 * LDIM,
      d_b_hi + coff + (size_t)j0 * LDIM, d_b_lo + coff + (size_t)j0 * LDIM};

  const int larr = tid >> 6;
  const int lrow = (tid & 63) * 2;
  const __nv_bfloat16* lsrc = gsrc[larr];
  const uint32_t lsmem = sbase + larr * ARRB + lrow * EROWB;

#define ISSUE_LOAD(buf, kc) do { \
    const char* g0 = (const char*)(lsrc + (size_t)lrow * LDIM + (kc)); \
    const char* g1 = (const char*)(lsrc + (size_t)(lrow + 1) * LDIM + (kc)); \
    uint32_t s0 = lsmem + (buf) * BUFB; \
    uint32_t s1 = s0 + EROWB; \
    CP_ASYNC16(s0,      g0);      CP_ASYNC16(s0 + 16, g0 + 16); \
    CP_ASYNC16(s0 + 32, g0 + 32); CP_ASYNC16(s0 + 48, g0 + 48); \
    CP_ASYNC16(s1,      g1);      CP_ASYNC16(s1 + 16, g1 + 16); \
    CP_ASYNC16(s1 + 32, g1 + 32); CP_ASYNC16(s1 + 48, g1 + 48); \
    CP_COMMIT(); \
  } while (0)

  const int w = tid >> 5, l = tid & 31;
  const int wm = w & 1, wn = w >> 1;
  const int a_r = l & 15, a_c = l >> 4;
  const int b_r = (l & 7) + ((l >> 4) << 3);
  const int b_c = (l >> 3) & 1;

  float acc[4][4][4];
#pragma unroll
  for (int mt = 0; mt < 4; mt++)
#pragma unroll
    for (int nt = 0; nt < 4; nt++)
#pragma unroll
      for (int q = 0; q < 4; q++) acc[mt][nt][q] = 0.f;

  ISSUE_LOAD(0, 0);

  for (int ci = 0; ci < 16; ci++) {
    const int buf = ci & 1;
    if (ci < 15) ISSUE_LOAD(buf ^ 1, (ci + 1) * 32);
    if (ci < 15) { CP_WAIT(1); } else { CP_WAIT(0); }
    __syncthreads();

    const uint32_t bufbase = sbase + buf * BUFB;
#pragma unroll
    for (int term = 0; term < 3; term++) {
      const uint32_t Ab = bufbase + (term == 1 ? ARRB : 0);
      const uint32_t Bb = bufbase + 2 * ARRB + (term == 2 ? ARRB : 0);
#pragma unroll
      for (int ks = 0; ks < 2; ks++) {
        uint32_t af[4][4], bf[2][4];
#pragma unroll
        for (int mt = 0; mt < 4; mt++) {
          uint32_t addr = Ab + (uint32_t)(wm * 64 + mt * 16 + a_r) * EROWB + ks * 32 + a_c * 16;
          LDSM_X4(af[mt][0], af[mt][1], af[mt][2], af[mt][3], addr);
        }
#pragma unroll
        for (int np = 0; np < 2; np++) {
          uint32_t addr = Bb + (uint32_t)(wn * 32 + np * 16 + b_r) * EROWB + ks * 32 + b_c * 16;
          LDSM_X4(bf[np][0], bf[np][1], bf[np][2], bf[np][3], addr);
        }
#pragma unroll
        for (int mt = 0; mt < 4; mt++) {
#pragma unroll
          for (int nt = 0; nt < 4; nt++) {
            uint32_t b0 = (nt & 1) ? bf[nt >> 1][2] : bf[nt >> 1][0];
            uint32_t b1 = (nt & 1) ? bf[nt >> 1][3] : bf[nt >> 1][1];
            MMA16816(acc[mt][nt], af[mt], b0, b1);
          }
        }
      }
    }
    __syncthreads();
  }

  float* mbase = d_mt + coff;
#pragma unroll
  for (int mt = 0; mt < 4; mt++) {
#pragma unroll
    for (int h = 0; h < 2; h++) {
      int row = i0 + wm * 64 + mt * 16 + (l >> 2) + h * 8;
      float* rp = mbase + (size_t)row * LDIM + j0 + wn * 32 + (l & 3) * 2;
#pragma unroll
      for (int nt = 0; nt < 4; nt++) {
        float2 v = make_float2(acc[mt][nt][h * 2], acc[mt][nt][h * 2 + 1]);
        *(float2*)(rp + nt * 8) = v;
      }
    }
  }
#undef ISSUE_LOAD
}

// ---------------- K3: LN(m) over c, @W_proj_out, * g * mask ----------------
__global__ __launch_bounds__(256) void k_out(
    const float* __restrict__ lnw, const float* __restrict__ lnb,
    const float* __restrict__ Wpo, const int* __restrict__ mask,
    float* __restrict__ out) {
  __shared__ float ms[CDIM][33];
  int i = blockIdx.y;
  int j0 = blockIdx.x * 32;
  int t = threadIdx.x;
  int lane = t & 31, warp = t >> 5;
#pragma unroll
  for (int q = 0; q < 16; q++) {
    int c = warp + 8 * q;
    ms[c][lane] = d_mt[(size_t)c * NROWS + (size_t)i * LDIM + j0 + lane];
  }
  __syncthreads();
  float w0 = lnw[lane], w1 = lnw[lane + 32], w2 = lnw[lane + 64], w3 = lnw[lane + 96];
  float b0 = lnb[lane], b1 = lnb[lane + 32], b2 = lnb[lane + 64], b3 = lnb[lane + 96];
#pragma unroll
  for (int s = 0; s < 4; s++) {
    int jj = warp * 4 + s;
    float x0 = ms[lane][jj], x1 = ms[lane + 32][jj];
    float x2 = ms[lane + 64][jj], x3 = ms[lane + 96][jj];
    float mu = warp_sum(x0 + x1 + x2 + x3) * (1.f / CDIM);
    float d0 = x0 - mu, d1 = x1 - mu, d2 = x2 - mu, d3 = x3 - mu;
    float var = warp_sum(d0 * d0 + d1 * d1 + d2 * d2 + d3 * d3) * (1.f / CDIM);
    float rstd = rsqrtf(var + EPSV);
    ms[lane][jj]      = d0 * rstd * w0 + b0;
    ms[lane + 32][jj] = d1 * rstd * w1 + b1;
    ms[lane + 64][jj] = d2 * rstd * w2 + b2;
    ms[lane + 96][jj] = d3 * rstd * w3 + b3;
  }
  __syncthreads();
  float acc[4][4] = {};
  for (int cch = 0; cch < CDIM; cch++) {
    float4 w4 = *(const float4*)(Wpo + cch * CDIM + lane * 4);
#pragma unroll
    for (int q = 0; q < 4; q++) {
      float mv = ms[cch][warp + 8 * q];
      acc[q][0] += mv * w4.x; acc[q][1] += mv * w4.y;
      acc[q][2] += mv * w4.z; acc[q][3] += mv * w4.w;
    }
  }
#pragma unroll
  for (int q = 0; q < 4; q++) {
    int j = j0 + warp + 8 * q;
    size_t n = (size_t)i * LDIM + j;
    float mkv = (float)mask[n];
    float4 g4 = *(const float4*)(d_g + n * CDIM + lane * 4);
    float4 o = make_float4(g4.x * acc[q][0] * mkv, g4.y * acc[q][1] * mkv,
                           g4.z * acc[q][2] * mkv, g4.w * acc[q][3] * mkv);
    *(float4*)(out + n * CDIM + lane * 4) = o;
  }
}

// ---------------- launch ----------------------------------------------------
extern "C" void kernel_launch(void* const* d_in, const int* in_sizes, int n_in,
                              void* d_out, int out_size) {
  const float* z        = (const float*)d_in[0];
  const int*   mask     = (const int*)  d_in[1];
  const float* ln_in_w  = (const float*)d_in[2];
  const float* ln_in_b  = (const float*)d_in[3];
  const float* ln_out_w = (const float*)d_in[4];
  const float* ln_out_b = (const float*)d_in[5];
  const float* Wpa = (const float*)d_in[6];
  const float* Wga = (const float*)d_in[7];
  const float* Wpb = (const float*)d_in[8];
  const float* Wgb = (const float*)d_in[9];
  const float* Wgo = (const float*)d_in[10];
  const float* Wpo = (const float*)d_in[11];
  float* out = (float*)d_out;

  cudaFuncSetAttribute(k_projmma, cudaFuncAttributeMaxDynamicSharedMemorySize, PROJ_SMEM);
  cudaFuncSetAttribute(k_einsum_mma, cudaFuncAttributeMaxDynamicSharedMemorySize, EIN_SMEM);

  k_prew<<<dim3(8, 5), 256>>>(Wga, Wpa, Wgb, Wpb, Wgo);
  k_projmma<<<NROWS / 128, 256, PROJ_SMEM>>>(z, mask, ln_in_w, ln_in_b);
  dim3 g2(LDIM / 128, LDIM / 128, CDIM);
  k_einsum_mma<<<g2, 256, EIN_SMEM>>>();
  dim3 g3(LDIM / 32, LDIM);
  k_out<<<g3, 256>>>(ln_out_w, ln_out_b, Wpo, mask, out);
}

// round 6
// speedup vs baseline: 1.9215x; 1.0999x over previous
#include <cuda_runtime.h>
#include <cuda_bf16.h>
#include <cstdint>

#define LDIM 512
#define CDIM 128
#define NROWS (LDIM * LDIM)   // 262144 pair rows
#define EPSV 1e-5f

// ---------------- scratch (static device memory; no runtime allocation) ----
__device__ float d_g  [(size_t)NROWS * CDIM];          // sigmoid(zln @ W_gate_out), [n][c]
__device__ __nv_bfloat16 d_a_hi[(size_t)CDIM * NROWS]; // a split: [c][i][k]
__device__ __nv_bfloat16 d_a_lo[(size_t)CDIM * NROWS];
__device__ __nv_bfloat16 d_b_hi[(size_t)CDIM * NROWS]; // b split: [c][j][k]
__device__ __nv_bfloat16 d_b_lo[(size_t)CDIM * NROWS];
__device__ float d_mt [(size_t)CDIM * NROWS];          // einsum result: [c][i][j]
// pre-transposed weights [w][ch][k] bf16 hi/lo (plain layout, B-operand rows)
__device__ __nv_bfloat16 d_w_hi[5 * CDIM * CDIM];
__device__ __nv_bfloat16 d_w_lo[5 * CDIM * CDIM];

// ---------------- arch-generic PTX helpers (plain sm_103 target!) ----------
__device__ __forceinline__ uint32_t smem_u32(const void* p) {
  uint32_t a;
  asm("{ .reg .u64 t; cvta.to.shared.u64 t, %1; cvt.u32.u64 %0, t; }" : "=r"(a) : "l"(p));
  return a;
}
#define CP_ASYNC16(s, g) \
  asm volatile("cp.async.cg.shared.global [%0], [%1], 16;" :: "r"(s), "l"(g) : "memory")
#define CP_COMMIT() asm volatile("cp.async.commit_group;" ::: "memory")
#define CP_WAIT(n)  asm volatile("cp.async.wait_group %0;" :: "n"(n) : "memory")

#define LDSM_X4(r0, r1, r2, r3, addr) \
  asm volatile("ldmatrix.sync.aligned.m8n8.x4.shared.b16 {%0,%1,%2,%3}, [%4];" \
    : "=r"(r0), "=r"(r1), "=r"(r2), "=r"(r3) : "r"(addr))

#define MMA16816(d, a, b0, b1) \
  asm volatile("mma.sync.aligned.m16n8k16.row.col.f32.bf16.bf16.f32 " \
    "{%0,%1,%2,%3}, {%4,%5,%6,%7}, {%8,%9}, {%0,%1,%2,%3};" \
    : "+f"((d)[0]), "+f"((d)[1]), "+f"((d)[2]), "+f"((d)[3]) \
    : "r"((a)[0]), "r"((a)[1]), "r"((a)[2]), "r"((a)[3]), "r"(b0), "r"(b1))

#define MOVMAT(d, s) \
  asm volatile("movmatrix.sync.aligned.m8n8.trans.b16 %0, %1;" : "=r"(d) : "r"(s))

__device__ __forceinline__ float warp_sum(float v) {
#pragma unroll
  for (int o = 16; o > 0; o >>= 1) v += __shfl_xor_sync(0xffffffffu, v, o);
  return v;
}
__device__ __forceinline__ float sigmoidf(float x) {
  return 1.f / (1.f + __expf(-x));
}
__device__ __forceinline__ unsigned pack2(float a, float b) {
  __nv_bfloat162 t = __floats2bfloat162_rn(a, b);
  return *(unsigned*)&t;
}

// ---------------- K_prew: W -> [ch][k] bf16 hi/lo (plain) -------------------
__global__ __launch_bounds__(256) void k_prew(
    const float* __restrict__ Wga, const float* __restrict__ Wpa,
    const float* __restrict__ Wgb, const float* __restrict__ Wpb,
    const float* __restrict__ Wgo) {
  const float* srcs[5] = {Wga, Wpa, Wgb, Wpb, Wgo};
  const float* W = srcs[blockIdx.y];
  int t = threadIdx.x;
  int ch = blockIdx.x * 16 + (t >> 4);
  int k0 = (t & 15) * 8;
  uint32_t hr[4], lr[4];
#pragma unroll
  for (int q = 0; q < 4; q++) {
    float v0 = W[(k0 + 2 * q) * CDIM + ch];
    float v1 = W[(k0 + 2 * q + 1) * CDIM + ch];
    float h0 = __bfloat162float(__float2bfloat16(v0));
    float h1 = __bfloat162float(__float2bfloat16(v1));
    hr[q] = pack2(h0, h1);
    lr[q] = pack2(v0 - h0, v1 - h1);
  }
  size_t off = (size_t)blockIdx.y * (CDIM * CDIM) + (size_t)ch * CDIM + k0;
  *(uint4*)(d_w_hi + off) = make_uint4(hr[0], hr[1], hr[2], hr[3]);
  *(uint4*)(d_w_lo + off) = make_uint4(lr[0], lr[1], lr[2], lr[3]);
}

// ---------------- K1: fused LN + 5-way projection on HMMA (M=64) ------------
// CTA: 64 pair rows, 2 CTAs/SM. A (zln hi/lo) K=128 resident, XOR swizzle.
// W staged in 1/8-K chunks (16 k) of 4 arrays {g_hi,g_lo,p_hi,p_lo},
// 3 smem buffers, padded pitch 48B (conflict-free ldmatrix, no XOR needed).
// 24 phases = 3 stages x 8 k-chunks. Stage 0=(Wga,Wpa)->a, 1=(Wgb,Wpb)->b, 2=Wgo->g.
#define APITCH 256
#define SA_BYTES (64 * APITCH)      // 16 KB per A array
#define WPITCH 48                   // 32B data + 16B pad
#define SW_ARR (128 * WPITCH)       // 6144 B per W array chunk
#define SW_BUF (4 * SW_ARR)         // 24576 B per buffer
#define PROJ_SMEM (2 * SA_BYTES + 3 * SW_BUF)   // 106496 B

__device__ __forceinline__ void proj_issue_chunk(int ph, int t, uint32_t sW) {
  int s = ph >> 3, e = ph & 7;
  int arr = t >> 6;          // {g_hi, g_lo, p_hi, p_lo}
  int ch = (t & 63) * 2;
  if (s < 2 || arr < 2) {    // stage 2 has only the gate weight
    int widx = s * 2 + (arr >> 1);
    const __nv_bfloat16* base = (arr & 1) ? d_w_lo : d_w_hi;
    const char* g = (const char*)(base + (size_t)widx * (CDIM * CDIM) +
                                  (size_t)ch * CDIM + e * 16);
    uint32_t d = sW + (ph % 3) * SW_BUF + arr * SW_ARR + ch * WPITCH;
    CP_ASYNC16(d, g);
    CP_ASYNC16(d + 16, g + 16);
    CP_ASYNC16(d + WPITCH, g + 2 * CDIM);
    CP_ASYNC16(d + WPITCH + 16, g + 2 * CDIM + 16);
  }
  CP_COMMIT();
}

__global__ __launch_bounds__(256, 2) void k_projmma(
    const float* __restrict__ z, const int* __restrict__ mask,
    const float* __restrict__ lnw, const float* __restrict__ lnb) {
  extern __shared__ char smem[];
  const uint32_t sbase = smem_u32(smem);
  const uint32_t sAhi = sbase, sW = sbase + 2 * SA_BYTES;
  const int n0 = blockIdx.x * 64;
  const int t = threadIdx.x, l = t & 31, w = t >> 5;

  proj_issue_chunk(0, t, sW);
  proj_issue_chunk(1, t, sW);

  // ---- LN: 64 rows, warp handles rows w, w+8, ... -------------------------
  {
    float4 wv = *(const float4*)(lnw + l * 4);
    float4 bv = *(const float4*)(lnb + l * 4);
#pragma unroll 4
    for (int it = 0; it < 8; it++) {
      int r = w + it * 8;
      float4 v = *(const float4*)(z + (size_t)(n0 + r) * CDIM + l * 4);
      float mu = warp_sum(v.x + v.y + v.z + v.w) * (1.f / CDIM);
      float dx = v.x - mu, dy = v.y - mu, dz = v.z - mu, dw = v.w - mu;
      float var = warp_sum(dx * dx + dy * dy + dz * dz + dw * dw) * (1.f / CDIM);
      float rstd = rsqrtf(var + EPSV);
      float o0 = dx * rstd * wv.x + bv.x, o1 = dy * rstd * wv.y + bv.y;
      float o2 = dz * rstd * wv.z + bv.z, o3 = dw * rstd * wv.w + bv.w;
      float h0 = __bfloat162float(__float2bfloat16(o0));
      float h1 = __bfloat162float(__float2bfloat16(o1));
      float h2 = __bfloat162float(__float2bfloat16(o2));
      float h3 = __bfloat162float(__float2bfloat16(o3));
      uint32_t off = r * APITCH + (((l >> 1) ^ (r & 7)) * 16) + (l & 1) * 8;
      *(uint2*)(smem + off) = make_uint2(pack2(h0, h1), pack2(h2, h3));
      *(uint2*)(smem + SA_BYTES + off) =
          make_uint2(pack2(o0 - h0, o1 - h1), pack2(o2 - h2, o3 - h3));
    }
  }
  __syncthreads();

  const int a_r = l & 15, a_c = l >> 4;
  const int b_r = (l & 7) + ((l >> 4) << 3), b_c = (l >> 3) & 1;
  const int wm = w & 1, wn = w >> 1;   // 2(M) x 4(N) warps, warp M-tile 32

  float mk[2][2];
#pragma unroll
  for (int mt = 0; mt < 2; mt++)
#pragma unroll
    for (int h = 0; h < 2; h++)
      mk[mt][h] = (float)mask[n0 + wm * 32 + mt * 16 + (l >> 2) + 8 * h];

  float accg[2][4][4], accp[2][4][4];

  for (int ph = 0; ph < 24; ph++) {
    const int s = ph >> 3, e = ph & 7;
    if (ph + 2 < 24) proj_issue_chunk(ph + 2, t, sW);
    if (ph < 22) { CP_WAIT(2); } else if (ph == 22) { CP_WAIT(1); } else { CP_WAIT(0); }
    __syncthreads();

    if (e == 0) {
#pragma unroll
      for (int mt = 0; mt < 2; mt++)
#pragma unroll
        for (int nt = 0; nt < 4; nt++)
#pragma unroll
          for (int q = 0; q < 4; q++) { accg[mt][nt][q] = 0.f; accp[mt][nt][q] = 0.f; }
    }

    const uint32_t wb = sW + (ph % 3) * SW_BUF;
    uint32_t ah[2][4], al[2][4];
#pragma unroll
    for (int mt = 0; mt < 2; mt++) {
      int row = wm * 32 + mt * 16 + a_r;
      uint32_t addr = sAhi + row * APITCH + (((e * 2 + a_c) ^ (row & 7)) * 16);
      LDSM_X4(ah[mt][0], ah[mt][1], ah[mt][2], ah[mt][3], addr);
      LDSM_X4(al[mt][0], al[mt][1], al[mt][2], al[mt][3], addr + SA_BYTES);
    }
#pragma unroll
    for (int gm = 0; gm < 2; gm++) {
      if (s == 2 && gm == 1) break;
      uint32_t bh[2][4], bl[2][4];
      const uint32_t Bh = wb + (gm * 2) * SW_ARR, Bl = Bh + SW_ARR;
#pragma unroll
      for (int np = 0; np < 2; np++) {
        uint32_t caddr = (uint32_t)(wn * 32 + np * 16 + b_r) * WPITCH + b_c * 16;
        LDSM_X4(bh[np][0], bh[np][1], bh[np][2], bh[np][3], Bh + caddr);
        LDSM_X4(bl[np][0], bl[np][1], bl[np][2], bl[np][3], Bl + caddr);
      }
#pragma unroll
      for (int mt = 0; mt < 2; mt++) {
#pragma unroll
        for (int nt = 0; nt < 4; nt++) {
          uint32_t h0 = (nt & 1) ? bh[nt >> 1][2] : bh[nt >> 1][0];
          uint32_t h1 = (nt & 1) ? bh[nt >> 1][3] : bh[nt >> 1][1];
          uint32_t l0 = (nt & 1) ? bl[nt >> 1][2] : bl[nt >> 1][0];
          uint32_t l1 = (nt & 1) ? bl[nt >> 1][3] : bl[nt >> 1][1];
          float* acc = gm ? accp[mt][nt] : accg[mt][nt];
          MMA16816(acc, ah[mt], h0, h1);
          MMA16816(acc, al[mt], h0, h1);
          MMA16816(acc, ah[mt], l0, l1);
        }
      }
    }

    if (e == 7) {      // stage epilogue
      if (s < 2) {
        __nv_bfloat16* dhi = s ? d_b_hi : d_a_hi;
        __nv_bfloat16* dlo = s ? d_b_lo : d_a_lo;
#pragma unroll
        for (int mt = 0; mt < 2; mt++) {
#pragma unroll
          for (int h = 0; h < 2; h++) {
            int nb = n0 + wm * 32 + mt * 16 + 8 * h + 2 * (l & 3);
#pragma unroll
            for (int nt = 0; nt < 4; nt++) {
              float v0 = sigmoidf(accg[mt][nt][2 * h]) * accp[mt][nt][2 * h] * mk[mt][h];
              float v1 = sigmoidf(accg[mt][nt][2 * h + 1]) * accp[mt][nt][2 * h + 1] * mk[mt][h];
              float h0 = __bfloat162float(__float2bfloat16(v0));
              float h1 = __bfloat162float(__float2bfloat16(v1));
              uint32_t hreg = pack2(h0, h1), lreg = pack2(v0 - h0, v1 - h1);
              uint32_t ht, lt;
              MOVMAT(ht, hreg);
              MOVMAT(lt, lreg);
              size_t chrow = (size_t)(wn * 32 + nt * 8 + (l >> 2));
              *(uint32_t*)(dhi + chrow * NROWS + nb) = ht;
              *(uint32_t*)(dlo + chrow * NROWS + nb) = lt;
            }
          }
        }
      } else {
#pragma unroll
        for (int mt = 0; mt < 2; mt++) {
#pragma unroll
          for (int h = 0; h < 2; h++) {
            int n = n0 + wm * 32 + mt * 16 + (l >> 2) + 8 * h;
            float* dst = d_g + (size_t)n * CDIM + wn * 32 + 2 * (l & 3);
#pragma unroll
            for (int nt = 0; nt < 4; nt++) {
              float2 o = make_float2(sigmoidf(accg[mt][nt][2 * h]),
                                     sigmoidf(accg[mt][nt][2 * h + 1]));
              *(float2*)(dst + nt * 8) = o;
            }
          }
        }
      }
    }
    __syncthreads();
  }
}

// ---------------- K2: channel-batched einsum on HMMA, frag-cached -----------
#define EROWB 80
#define ARRB (128 * EROWB)
#define BUFB (4 * ARRB)
#define EIN_SMEM (2 * BUFB)

__global__ __launch_bounds__(256, 2) void k_einsum_mma() {
  extern __shared__ char smem[];
  const uint32_t sbase = smem_u32(smem);
  const int c = blockIdx.z;
  const int i0 = blockIdx.x * 128, j0 = blockIdx.y * 128;
  const int tid = threadIdx.x;
  const size_t coff = (size_t)c * NROWS;

  const __nv_bfloat16* gsrc[4] = {
      d_a_hi + coff + (size_t)i0 * LDIM, d_a_lo + coff + (size_t)i0 * LDIM,
      d_b_hi + coff + (size_t)j0 * LDIM, d_b_lo + coff + (size_t)j0 * LDIM};

  const int larr = tid >> 6;
  const int lrow = (tid & 63) * 2;
  const __nv_bfloat16* lsrc = gsrc[larr];
  const uint32_t lsmem = sbase + larr * ARRB + lrow * EROWB;

#define ISSUE_LOAD(buf, kc) do { \
    const char* g0 = (const char*)(lsrc + (size_t)lrow * LDIM + (kc)); \
    const char* g1 = (const char*)(lsrc + (size_t)(lrow + 1) * LDIM + (kc)); \
    uint32_t s0 = lsmem + (buf) * BUFB; \
    uint32_t s1 = s0 + EROWB; \
    CP_ASYNC16(s0,      g0);      CP_ASYNC16(s0 + 16, g0 + 16); \
    CP_ASYNC16(s0 + 32, g0 + 32); CP_ASYNC16(s0 + 48, g0 + 48); \
    CP_ASYNC16(s1,      g1);      CP_ASYNC16(s1 + 16, g1 + 16); \
    CP_ASYNC16(s1 + 32, g1 + 32); CP_ASYNC16(s1 + 48, g1 + 48); \
    CP_COMMIT(); \
  } while (0)

  const int w = tid >> 5, l = tid & 31;
  const int wm = w & 1, wn = w >> 1;
  const int a_r = l & 15, a_c = l >> 4;
  const int b_r = (l & 7) + ((l >> 4) << 3);
  const int b_c = (l >> 3) & 1;

  float acc[4][4][4];
#pragma unroll
  for (int mt = 0; mt < 4; mt++)
#pragma unroll
    for (int nt = 0; nt < 4; nt++)
#pragma unroll
      for (int q = 0; q < 4; q++) acc[mt][nt][q] = 0.f;

  ISSUE_LOAD(0, 0);

  for (int ci = 0; ci < 16; ci++) {
    const int buf = ci & 1;
    if (ci < 15) ISSUE_LOAD(buf ^ 1, (ci + 1) * 32);
    if (ci < 15) { CP_WAIT(1); } else { CP_WAIT(0); }
    __syncthreads();

    const uint32_t bufbase = sbase + buf * BUFB;
#pragma unroll
    for (int ks = 0; ks < 2; ks++) {
      const uint32_t kof = ks * 32 + a_c * 16;
      const uint32_t kofb = ks * 32 + b_c * 16;
      uint32_t ah[4][4], bh[2][4];
      // hi fragments
#pragma unroll
      for (int mt = 0; mt < 4; mt++) {
        uint32_t addr = bufbase + (uint32_t)(wm * 64 + mt * 16 + a_r) * EROWB + kof;
        LDSM_X4(ah[mt][0], ah[mt][1], ah[mt][2], ah[mt][3], addr);
      }
#pragma unroll
      for (int np = 0; np < 2; np++) {
        uint32_t addr = bufbase + 2 * ARRB + (uint32_t)(wn * 32 + np * 16 + b_r) * EROWB + kofb;
        LDSM_X4(bh[np][0], bh[np][1], bh[np][2], bh[np][3], addr);
      }
      // term 1: hi*hi
#pragma unroll
      for (int mt = 0; mt < 4; mt++)
#pragma unroll
        for (int nt = 0; nt < 4; nt++) {
          uint32_t b0 = (nt & 1) ? bh[nt >> 1][2] : bh[nt >> 1][0];
          uint32_t b1 = (nt & 1) ? bh[nt >> 1][3] : bh[nt >> 1][1];
          MMA16816(acc[mt][nt], ah[mt], b0, b1);
        }
      // term 2: lo*hi (A_lo x B_hi)
      {
        uint32_t alq[4][4];
#pragma unroll
        for (int mt = 0; mt < 4; mt++) {
          uint32_t addr = bufbase + ARRB + (uint32_t)(wm * 64 + mt * 16 + a_r) * EROWB + kof;
          LDSM_X4(alq[mt][0], alq[mt][1], alq[mt][2], alq[mt][3], addr);
        }
#pragma unroll
        for (int mt = 0; mt < 4; mt++)
#pragma unroll
          for (int nt = 0; nt < 4; nt++) {
            uint32_t b0 = (nt & 1) ? bh[nt >> 1][2] : bh[nt >> 1][0];
            uint32_t b1 = (nt & 1) ? bh[nt >> 1][3] : bh[nt >> 1][1];
            MMA16816(acc[mt][nt], alq[mt], b0, b1);
          }
      }
      // term 3: hi*lo (A_hi x B_lo)
      {
        uint32_t blq[2][4];
#pragma unroll
        for (int np = 0; np < 2; np++) {
          uint32_t addr = bufbase + 3 * ARRB + (uint32_t)(wn * 32 + np * 16 + b_r) * EROWB + kofb;
          LDSM_X4(blq[np][0], blq[np][1], blq[np][2], blq[np][3], addr);
        }
#pragma unroll
        for (int mt = 0; mt < 4; mt++)
#pragma unroll
          for (int nt = 0; nt < 4; nt++) {
            uint32_t b0 = (nt & 1) ? blq[nt >> 1][2] : blq[nt >> 1][0];
            uint32_t b1 = (nt & 1) ? blq[nt >> 1][3] : blq[nt >> 1][1];
            MMA16816(acc[mt][nt], ah[mt], b0, b1);
          }
      }
    }
    __syncthreads();
  }

  float* mbase = d_mt + coff;
#pragma unroll
  for (int mt = 0; mt < 4; mt++) {
#pragma unroll
    for (int h = 0; h < 2; h++) {
      int row = i0 + wm * 64 + mt * 16 + (l >> 2) + h * 8;
      float* rp = mbase + (size_t)row * LDIM + j0 + wn * 32 + (l & 3) * 2;
#pragma unroll
      for (int nt = 0; nt < 4; nt++) {
        float2 v = make_float2(acc[mt][nt][h * 2], acc[mt][nt][h * 2 + 1]);
        *(float2*)(rp + nt * 8) = v;
      }
    }
  }
#undef ISSUE_LOAD
}

// ---------------- K3: LN(m) over c, @W_proj_out, * g * mask (64-wide) -------
__global__ __launch_bounds__(256) void k_out(
    const float* __restrict__ lnw, const float* __restrict__ lnb,
    const float* __restrict__ Wpo, const int* __restrict__ mask,
    float* __restrict__ out) {
  __shared__ float ms[CDIM][65];
  int i = blockIdx.y;
  int j0 = blockIdx.x * 64;
  int t = threadIdx.x;
  int lane = t & 31, warp = t >> 5;
#pragma unroll
  for (int q = 0; q < 16; q++) {
    int c = warp + 8 * q;
    const float* src = d_mt + (size_t)c * NROWS + (size_t)i * LDIM + j0;
    ms[c][lane] = src[lane];
    ms[c][32 + lane] = src[32 + lane];
  }
  __syncthreads();
  float w0 = lnw[lane], w1 = lnw[lane + 32], w2 = lnw[lane + 64], w3 = lnw[lane + 96];
  float b0 = lnb[lane], b1 = lnb[lane + 32], b2 = lnb[lane + 64], b3 = lnb[lane + 96];
#pragma unroll
  for (int s = 0; s < 8; s++) {
    int jj = warp * 8 + s;
    float x0 = ms[lane][jj], x1 = ms[lane + 32][jj];
    float x2 = ms[lane + 64][jj], x3 = ms[lane + 96][jj];
    float mu = warp_sum(x0 + x1 + x2 + x3) * (1.f / CDIM);
    float d0 = x0 - mu, d1 = x1 - mu, d2 = x2 - mu, d3 = x3 - mu;
    float var = warp_sum(d0 * d0 + d1 * d1 + d2 * d2 + d3 * d3) * (1.f / CDIM);
    float rstd = rsqrtf(var + EPSV);
    ms[lane][jj]      = d0 * rstd * w0 + b0;
    ms[lane + 32][jj] = d1 * rstd * w1 + b1;
    ms[lane + 64][jj] = d2 * rstd * w2 + b2;
    ms[lane + 96][jj] = d3 * rstd * w3 + b3;
  }
  __syncthreads();
  float acc[8][4];
#pragma unroll
  for (int q = 0; q < 8; q++)
#pragma unroll
    for (int e = 0; e < 4; e++) acc[q][e] = 0.f;
  for (int cch = 0; cch < CDIM; cch++) {
    float4 w4 = *(const float4*)(Wpo + cch * CDIM + lane * 4);
#pragma unroll
    for (int q = 0; q < 8; q++) {
      float mv = ms[cch][warp * 8 + q];
      acc[q][0] += mv * w4.x; acc[q][1] += mv * w4.y;
      acc[q][2] += mv * w4.z; acc[q][3] += mv * w4.w;
    }
  }
#pragma unroll
  for (int q = 0; q < 8; q++) {
    int j = j0 + warp * 8 + q;
    size_t n = (size_t)i * LDIM + j;
    float mkv = (float)mask[n];
    float4 g4 = *(const float4*)(d_g + n * CDIM + lane * 4);
    float4 o = make_float4(g4.x * acc[q][0] * mkv, g4.y * acc[q][1] * mkv,
                           g4.z * acc[q][2] * mkv, g4.w * acc[q][3] * mkv);
    *(float4*)(out + n * CDIM + lane * 4) = o;
  }
}

// ---------------- launch ----------------------------------------------------
extern "C" void kernel_launch(void* const* d_in, const int* in_sizes, int n_in,
                              void* d_out, int out_size) {
  const float* z        = (const float*)d_in[0];
  const int*   mask     = (const int*)  d_in[1];
  const float* ln_in_w  = (const float*)d_in[2];
  const float* ln_in_b  = (const float*)d_in[3];
  const float* ln_out_w = (const float*)d_in[4];
  const float* ln_out_b = (const float*)d_in[5];
  const float* Wpa = (const float*)d_in[6];
  const float* Wga = (const float*)d_in[7];
  const float* Wpb = (const float*)d_in[8];
  const float* Wgb = (const float*)d_in[9];
  const float* Wgo = (const float*)d_in[10];
  const float* Wpo = (const float*)d_in[11];
  float* out = (float*)d_out;

  cudaFuncSetAttribute(k_projmma, cudaFuncAttributeMaxDynamicSharedMemorySize, PROJ_SMEM);
  cudaFuncSetAttribute(k_einsum_mma, cudaFuncAttributeMaxDynamicSharedMemorySize, EIN_SMEM);

  k_prew<<<dim3(8, 5), 256>>>(Wga, Wpa, Wgb, Wpb, Wgo);
  k_projmma<<<NROWS / 64, 256, PROJ_SMEM>>>(z, mask, ln_in_w, ln_in_b);
  dim3 g2(LDIM / 128, LDIM / 128, CDIM);
  k_einsum_mma<<<g2, 256, EIN_SMEM>>>();
  dim3 g3(LDIM / 64, LDIM);
  k_out<<<g3, 256>>>(ln_out_w, ln_out_b, Wpo, mask, out);
}

// round 7
// speedup vs baseline: 2.0347x; 1.0589x over previous
#include <cuda_runtime.h>
#include <cuda_bf16.h>
#include <cuda_fp16.h>
#include <cstdint>

#define LDIM 512
#define CDIM 128
#define NROWS (LDIM * LDIM)   // 262144 pair rows
#define EPSV 1e-5f

// ---------------- scratch (static device memory; no runtime allocation) ----
__device__ float d_g  [(size_t)NROWS * CDIM];      // sigmoid(zln @ W_gate_out), [n][c]
__device__ __half d_a_hi[(size_t)CDIM * NROWS];    // a split: [c][i][k]  (fp16)
__device__ __half d_a_lo[(size_t)CDIM * NROWS];
__device__ __half d_b_hi[(size_t)CDIM * NROWS];    // b hi only: [c][j][k]
__device__ float d_mt [(size_t)CDIM * NROWS];      // einsum result: [c][i][j]
// pre-transposed weights [w][ch][k] bf16 hi/lo; slots: Wga,Wpa,Wgb,Wpb,Wgo,Wpo
__device__ __nv_bfloat16 d_w_hi[6 * CDIM * CDIM];
__device__ __nv_bfloat16 d_w_lo[6 * CDIM * CDIM];

// ---------------- arch-generic PTX helpers (plain sm_103 target!) ----------
__device__ __forceinline__ uint32_t smem_u32(const void* p) {
  uint32_t a;
  asm("{ .reg .u64 t; cvta.to.shared.u64 t, %1; cvt.u32.u64 %0, t; }" : "=r"(a) : "l"(p));
  return a;
}
#define CP_ASYNC16(s, g) \
  asm volatile("cp.async.cg.shared.global [%0], [%1], 16;" :: "r"(s), "l"(g) : "memory")
#define CP_COMMIT() asm volatile("cp.async.commit_group;" ::: "memory")
#define CP_WAIT(n)  asm volatile("cp.async.wait_group %0;" :: "n"(n) : "memory")

#define LDSM_X4(r0, r1, r2, r3, addr) \
  asm volatile("ldmatrix.sync.aligned.m8n8.x4.shared.b16 {%0,%1,%2,%3}, [%4];" \
    : "=r"(r0), "=r"(r1), "=r"(r2), "=r"(r3) : "r"(addr))

#define MMA16816(d, a, b0, b1) \
  asm volatile("mma.sync.aligned.m16n8k16.row.col.f32.bf16.bf16.f32 " \
    "{%0,%1,%2,%3}, {%4,%5,%6,%7}, {%8,%9}, {%0,%1,%2,%3};" \
    : "+f"((d)[0]), "+f"((d)[1]), "+f"((d)[2]), "+f"((d)[3]) \
    : "r"((a)[0]), "r"((a)[1]), "r"((a)[2]), "r"((a)[3]), "r"(b0), "r"(b1))

#define MMAH16816(d, a, b0, b1) \
  asm volatile("mma.sync.aligned.m16n8k16.row.col.f32.f16.f16.f32 " \
    "{%0,%1,%2,%3}, {%4,%5,%6,%7}, {%8,%9}, {%0,%1,%2,%3};" \
    : "+f"((d)[0]), "+f"((d)[1]), "+f"((d)[2]), "+f"((d)[3]) \
    : "r"((a)[0]), "r"((a)[1]), "r"((a)[2]), "r"((a)[3]), "r"(b0), "r"(b1))

#define MOVMAT(d, s) \
  asm volatile("movmatrix.sync.aligned.m8n8.trans.b16 %0, %1;" : "=r"(d) : "r"(s))

__device__ __forceinline__ float warp_sum(float v) {
#pragma unroll
  for (int o = 16; o > 0; o >>= 1) v += __shfl_xor_sync(0xffffffffu, v, o);
  return v;
}
__device__ __forceinline__ float sigmoidf(float x) {
  return 1.f / (1.f + __expf(-x));
}
__device__ __forceinline__ unsigned pack2(float a, float b) {
  __nv_bfloat162 t = __floats2bfloat162_rn(a, b);
  return *(unsigned*)&t;
}
__device__ __forceinline__ unsigned pack2h(float a, float b) {
  __half2 t = __floats2half2_rn(a, b);
  return *(unsigned*)&t;
}

// ---------------- K_prew: W -> [ch][k] bf16 hi/lo (plain), 6 weights --------
__global__ __launch_bounds__(256) void k_prew(
    const float* __restrict__ Wga, const float* __restrict__ Wpa,
    const float* __restrict__ Wgb, const float* __restrict__ Wpb,
    const float* __restrict__ Wgo, const float* __restrict__ Wpo) {
  const float* srcs[6] = {Wga, Wpa, Wgb, Wpb, Wgo, Wpo};
  const float* W = srcs[blockIdx.y];
  int t = threadIdx.x;
  int ch = blockIdx.x * 16 + (t >> 4);
  int k0 = (t & 15) * 8;
  uint32_t hr[4], lr[4];
#pragma unroll
  for (int q = 0; q < 4; q++) {
    float v0 = W[(k0 + 2 * q) * CDIM + ch];
    float v1 = W[(k0 + 2 * q + 1) * CDIM + ch];
    float h0 = __bfloat162float(__float2bfloat16(v0));
    float h1 = __bfloat162float(__float2bfloat16(v1));
    hr[q] = pack2(h0, h1);
    lr[q] = pack2(v0 - h0, v1 - h1);
  }
  size_t off = (size_t)blockIdx.y * (CDIM * CDIM) + (size_t)ch * CDIM + k0;
  *(uint4*)(d_w_hi + off) = make_uint4(hr[0], hr[1], hr[2], hr[3]);
  *(uint4*)(d_w_lo + off) = make_uint4(lr[0], lr[1], lr[2], lr[3]);
}

// ---------------- K1: fused LN + 5-way projection on HMMA (M=64) ------------
#define APITCH 256
#define SA_BYTES (64 * APITCH)      // 16 KB per A array
#define WPITCH 48                   // 32B data + 16B pad
#define SW_ARR (128 * WPITCH)       // 6144 B per W array chunk
#define SW_BUF (4 * SW_ARR)         // 24576 B per buffer
#define PROJ_SMEM (2 * SA_BYTES + 3 * SW_BUF)   // 106496 B

__device__ __forceinline__ void proj_issue_chunk(int ph, int t, uint32_t sW) {
  int s = ph >> 3, e = ph & 7;
  int arr = t >> 6;          // {g_hi, g_lo, p_hi, p_lo}
  int ch = (t & 63) * 2;
  if (s < 2 || arr < 2) {
    int widx = s * 2 + (arr >> 1);
    const __nv_bfloat16* base = (arr & 1) ? d_w_lo : d_w_hi;
    const char* g = (const char*)(base + (size_t)widx * (CDIM * CDIM) +
                                  (size_t)ch * CDIM + e * 16);
    uint32_t d = sW + (ph % 3) * SW_BUF + arr * SW_ARR + ch * WPITCH;
    CP_ASYNC16(d, g);
    CP_ASYNC16(d + 16, g + 16);
    CP_ASYNC16(d + WPITCH, g + 2 * CDIM);
    CP_ASYNC16(d + WPITCH + 16, g + 2 * CDIM + 16);
  }
  CP_COMMIT();
}

__global__ __launch_bounds__(256, 2) void k_projmma(
    const float* __restrict__ z, const int* __restrict__ mask,
    const float* __restrict__ lnw, const float* __restrict__ lnb) {
  extern __shared__ char smem[];
  const uint32_t sbase = smem_u32(smem);
  const uint32_t sAhi = sbase, sW = sbase + 2 * SA_BYTES;
  const int n0 = blockIdx.x * 64;
  const int t = threadIdx.x, l = t & 31, w = t >> 5;

  proj_issue_chunk(0, t, sW);
  proj_issue_chunk(1, t, sW);

  {
    float4 wv = *(const float4*)(lnw + l * 4);
    float4 bv = *(const float4*)(lnb + l * 4);
#pragma unroll 4
    for (int it = 0; it < 8; it++) {
      int r = w + it * 8;
      float4 v = *(const float4*)(z + (size_t)(n0 + r) * CDIM + l * 4);
      float mu = warp_sum(v.x + v.y + v.z + v.w) * (1.f / CDIM);
      float dx = v.x - mu, dy = v.y - mu, dz = v.z - mu, dw = v.w - mu;
      float var = warp_sum(dx * dx + dy * dy + dz * dz + dw * dw) * (1.f / CDIM);
      float rstd = rsqrtf(var + EPSV);
      float o0 = dx * rstd * wv.x + bv.x, o1 = dy * rstd * wv.y + bv.y;
      float o2 = dz * rstd * wv.z + bv.z, o3 = dw * rstd * wv.w + bv.w;
      float h0 = __bfloat162float(__float2bfloat16(o0));
      float h1 = __bfloat162float(__float2bfloat16(o1));
      float h2 = __bfloat162float(__float2bfloat16(o2));
      float h3 = __bfloat162float(__float2bfloat16(o3));
      uint32_t off = r * APITCH + (((l >> 1) ^ (r & 7)) * 16) + (l & 1) * 8;
      *(uint2*)(smem + off) = make_uint2(pack2(h0, h1), pack2(h2, h3));
      *(uint2*)(smem + SA_BYTES + off) =
          make_uint2(pack2(o0 - h0, o1 - h1), pack2(o2 - h2, o3 - h3));
    }
  }
  __syncthreads();

  const int a_r = l & 15, a_c = l >> 4;
  const int b_r = (l & 7) + ((l >> 4) << 3), b_c = (l >> 3) & 1;
  const int wm = w & 1, wn = w >> 1;

  float mk[2][2];
#pragma unroll
  for (int mt = 0; mt < 2; mt++)
#pragma unroll
    for (int h = 0; h < 2; h++)
      mk[mt][h] = (float)mask[n0 + wm * 32 + mt * 16 + (l >> 2) + 8 * h];

  float accg[2][4][4], accp[2][4][4];

  for (int ph = 0; ph < 24; ph++) {
    const int s = ph >> 3, e = ph & 7;
    if (ph + 2 < 24) proj_issue_chunk(ph + 2, t, sW);
    if (ph < 22) { CP_WAIT(2); } else if (ph == 22) { CP_WAIT(1); } else { CP_WAIT(0); }
    __syncthreads();

    if (e == 0) {
#pragma unroll
      for (int mt = 0; mt < 2; mt++)
#pragma unroll
        for (int nt = 0; nt < 4; nt++)
#pragma unroll
          for (int q = 0; q < 4; q++) { accg[mt][nt][q] = 0.f; accp[mt][nt][q] = 0.f; }
    }

    const uint32_t wb = sW + (ph % 3) * SW_BUF;
    uint32_t ah[2][4], al[2][4];
#pragma unroll
    for (int mt = 0; mt < 2; mt++) {
      int row = wm * 32 + mt * 16 + a_r;
      uint32_t addr = sAhi + row * APITCH + (((e * 2 + a_c) ^ (row & 7)) * 16);
      LDSM_X4(ah[mt][0], ah[mt][1], ah[mt][2], ah[mt][3], addr);
      LDSM_X4(al[mt][0], al[mt][1], al[mt][2], al[mt][3], addr + SA_BYTES);
    }
#pragma unroll
    for (int gm = 0; gm < 2; gm++) {
      if (s == 2 && gm == 1) break;
      uint32_t bh[2][4], bl[2][4];
      const uint32_t Bh = wb + (gm * 2) * SW_ARR, Bl = Bh + SW_ARR;
#pragma unroll
      for (int np = 0; np < 2; np++) {
        uint32_t caddr = (uint32_t)(wn * 32 + np * 16 + b_r) * WPITCH + b_c * 16;
        LDSM_X4(bh[np][0], bh[np][1], bh[np][2], bh[np][3], Bh + caddr);
        LDSM_X4(bl[np][0], bl[np][1], bl[np][2], bl[np][3], Bl + caddr);
      }
#pragma unroll
      for (int mt = 0; mt < 2; mt++) {
#pragma unroll
        for (int nt = 0; nt < 4; nt++) {
          uint32_t h0 = (nt & 1) ? bh[nt >> 1][2] : bh[nt >> 1][0];
          uint32_t h1 = (nt & 1) ? bh[nt >> 1][3] : bh[nt >> 1][1];
          uint32_t l0 = (nt & 1) ? bl[nt >> 1][2] : bl[nt >> 1][0];
          uint32_t l1 = (nt & 1) ? bl[nt >> 1][3] : bl[nt >> 1][1];
          float* acc = gm ? accp[mt][nt] : accg[mt][nt];
          MMA16816(acc, ah[mt], h0, h1);
          MMA16816(acc, al[mt], h0, h1);
          MMA16816(acc, ah[mt], l0, l1);
        }
      }
    }

    if (e == 7) {
      if (s == 0) {                 // a: fp16 hi + lo
#pragma unroll
        for (int mt = 0; mt < 2; mt++) {
#pragma unroll
          for (int h = 0; h < 2; h++) {
            int nb = n0 + wm * 32 + mt * 16 + 8 * h + 2 * (l & 3);
#pragma unroll
            for (int nt = 0; nt < 4; nt++) {
              float v0 = sigmoidf(accg[mt][nt][2 * h]) * accp[mt][nt][2 * h] * mk[mt][h];
              float v1 = sigmoidf(accg[mt][nt][2 * h + 1]) * accp[mt][nt][2 * h + 1] * mk[mt][h];
              __half q0 = __float2half_rn(v0), q1 = __float2half_rn(v1);
              uint32_t hreg = ((uint32_t)__half_as_ushort(q1) << 16) | __half_as_ushort(q0);
              uint32_t lreg = pack2h(v0 - __half2float(q0), v1 - __half2float(q1));
              uint32_t ht, lt;
              MOVMAT(ht, hreg);
              MOVMAT(lt, lreg);
              size_t chrow = (size_t)(wn * 32 + nt * 8 + (l >> 2));
              *(uint32_t*)(d_a_hi + chrow * NROWS + nb) = ht;
              *(uint32_t*)(d_a_lo + chrow * NROWS + nb) = lt;
            }
          }
        }
      } else if (s == 1) {          // b: fp16 hi only
#pragma unroll
        for (int mt = 0; mt < 2; mt++) {
#pragma unroll
          for (int h = 0; h < 2; h++) {
            int nb = n0 + wm * 32 + mt * 16 + 8 * h + 2 * (l & 3);
#pragma unroll
            for (int nt = 0; nt < 4; nt++) {
              float v0 = sigmoidf(accg[mt][nt][2 * h]) * accp[mt][nt][2 * h] * mk[mt][h];
              float v1 = sigmoidf(accg[mt][nt][2 * h + 1]) * accp[mt][nt][2 * h + 1] * mk[mt][h];
              uint32_t hreg = pack2h(v0, v1);
              uint32_t ht;
              MOVMAT(ht, hreg);
              size_t chrow = (size_t)(wn * 32 + nt * 8 + (l >> 2));
              *(uint32_t*)(d_b_hi + chrow * NROWS + nb) = ht;
            }
          }
        }
      } else {                      // g
#pragma unroll
        for (int mt = 0; mt < 2; mt++) {
#pragma unroll
          for (int h = 0; h < 2; h++) {
            int n = n0 + wm * 32 + mt * 16 + (l >> 2) + 8 * h;
            float* dst = d_g + (size_t)n * CDIM + wn * 32 + 2 * (l & 3);
#pragma unroll
            for (int nt = 0; nt < 4; nt++) {
              float2 o = make_float2(sigmoidf(accg[mt][nt][2 * h]),
                                     sigmoidf(accg[mt][nt][2 * h + 1]));
              *(float2*)(dst + nt * 8) = o;
            }
          }
        }
      }
    }
    __syncthreads();
  }
}

// ---------------- K2: channel-batched einsum, fp16 2-term -------------------
// staged arrays per chunk: a_hi, a_lo (M side), b_hi (N side)
#define EROWB 80
#define ARRB (128 * EROWB)
#define BUFB (3 * ARRB)             // 30720
#define EIN_SMEM (2 * BUFB)         // 61440

__global__ __launch_bounds__(256, 2) void k_einsum_mma() {
  extern __shared__ char smem[];
  const uint32_t sbase = smem_u32(smem);
  const int c = blockIdx.z;
  const int i0 = blockIdx.x * 128, j0 = blockIdx.y * 128;
  const int tid = threadIdx.x;
  const size_t coff = (size_t)c * NROWS;

  const int larr = tid >> 6;
  const bool tworow = larr < 2;
  const __half* lsrc;
  int lrow;
  uint32_t lsmem;
  if (tworow) {
    lsrc = (larr ? d_a_lo : d_a_hi) + coff + (size_t)i0 * LDIM;
    lrow = (tid & 63) * 2;
    lsmem = sbase + larr * ARRB + lrow * EROWB;
  } else {
    lsrc = d_b_hi + coff + (size_t)j0 * LDIM;
    lrow = (larr - 2) * 64 + (tid & 63);
    lsmem = sbase + 2 * ARRB + lrow * EROWB;
  }

#define ISSUE_LOAD(buf, kc) do { \
    const char* g0 = (const char*)(lsrc + (size_t)lrow * LDIM + (kc)); \
    uint32_t s0 = lsmem + (buf) * BUFB; \
    CP_ASYNC16(s0,      g0);      CP_ASYNC16(s0 + 16, g0 + 16); \
    CP_ASYNC16(s0 + 32, g0 + 32); CP_ASYNC16(s0 + 48, g0 + 48); \
    if (tworow) { \
      const char* g1 = (const char*)(lsrc + (size_t)(lrow + 1) * LDIM + (kc)); \
      uint32_t s1 = s0 + EROWB; \
      CP_ASYNC16(s1,      g1);      CP_ASYNC16(s1 + 16, g1 + 16); \
      CP_ASYNC16(s1 + 32, g1 + 32); CP_ASYNC16(s1 + 48, g1 + 48); \
    } \
    CP_COMMIT(); \
  } while (0)

  const int w = tid >> 5, l = tid & 31;
  const int wm = w & 1, wn = w >> 1;
  const int a_r = l & 15, a_c = l >> 4;
  const int b_r = (l & 7) + ((l >> 4) << 3);
  const int b_c = (l >> 3) & 1;

  float acc[4][4][4];
#pragma unroll
  for (int mt = 0; mt < 4; mt++)
#pragma unroll
    for (int nt = 0; nt < 4; nt++)
#pragma unroll
      for (int q = 0; q < 4; q++) acc[mt][nt][q] = 0.f;

  ISSUE_LOAD(0, 0);

  for (int ci = 0; ci < 16; ci++) {
    const int buf = ci & 1;
    if (ci < 15) ISSUE_LOAD(buf ^ 1, (ci + 1) * 32);
    if (ci < 15) { CP_WAIT(1); } else { CP_WAIT(0); }
    __syncthreads();

    const uint32_t bufbase = sbase + buf * BUFB;
#pragma unroll
    for (int ks = 0; ks < 2; ks++) {
      const uint32_t kof = ks * 32 + a_c * 16;
      const uint32_t kofb = ks * 32 + b_c * 16;
      uint32_t ah[4][4], alq[4][4], bh[2][4];
#pragma unroll
      for (int mt = 0; mt < 4; mt++) {
        uint32_t addr = bufbase + (uint32_t)(wm * 64 + mt * 16 + a_r) * EROWB + kof;
        LDSM_X4(ah[mt][0], ah[mt][1], ah[mt][2], ah[mt][3], addr);
        LDSM_X4(alq[mt][0], alq[mt][1], alq[mt][2], alq[mt][3], addr + ARRB);
      }
#pragma unroll
      for (int np = 0; np < 2; np++) {
        uint32_t addr = bufbase + 2 * ARRB + (uint32_t)(wn * 32 + np * 16 + b_r) * EROWB + kofb;
        LDSM_X4(bh[np][0], bh[np][1], bh[np][2], bh[np][3], addr);
      }
#pragma unroll
      for (int mt = 0; mt < 4; mt++)
#pragma unroll
        for (int nt = 0; nt < 4; nt++) {
          uint32_t b0 = (nt & 1) ? bh[nt >> 1][2] : bh[nt >> 1][0];
          uint32_t b1 = (nt & 1) ? bh[nt >> 1][3] : bh[nt >> 1][1];
          MMAH16816(acc[mt][nt], ah[mt], b0, b1);
          MMAH16816(acc[mt][nt], alq[mt], b0, b1);
        }
    }
    __syncthreads();
  }

  float* mbase = d_mt + coff;
#pragma unroll
  for (int mt = 0; mt < 4; mt++) {
#pragma unroll
    for (int h = 0; h < 2; h++) {
      int row = i0 + wm * 64 + mt * 16 + (l >> 2) + h * 8;
      float* rp = mbase + (size_t)row * LDIM + j0 + wn * 32 + (l & 3) * 2;
#pragma unroll
      for (int nt = 0; nt < 4; nt++) {
        float2 v = make_float2(acc[mt][nt][h * 2], acc[mt][nt][h * 2 + 1]);
        *(float2*)(rp + nt * 8) = v;
      }
    }
  }
#undef ISSUE_LOAD
}

// ---------------- K3: LN(m) + @W_proj_out on HMMA ---------------------------
// CTA: one i, 64 j values. m gathered to smem [jj][c], LN over c, bf16 hi/lo
// A-tiles, 3-term MMA vs pre-split Wpo (slot 5), epilogue * g * mask.
#define MSW 129
#define KO_MS_BYTES (64 * MSW * 4)                 // 33024
#define KO_SA (KO_MS_BYTES)                        // A hi at 33024
#define KO_SA_BYTES (64 * 256)                     // 16384 per array
#define KO_SW (KO_SA + 2 * KO_SA_BYTES)            // 65792
#define KO_SW_BYTES (128 * 256)                    // 32768 per array
#define KO_SMEM (KO_SW + 2 * KO_SW_BYTES)          // 131328

__global__ __launch_bounds__(256, 1) void k_outmma(
    const float* __restrict__ lnw, const float* __restrict__ lnb,
    const int* __restrict__ mask, float* __restrict__ out) {
  extern __shared__ char smem[];
  const uint32_t sbase = smem_u32(smem);
  float* msf = (float*)smem;
  const int i = blockIdx.y;
  const int j0 = blockIdx.x * 64;
  const int t = threadIdx.x, l = t & 31, w = t >> 5;

  // stage Wpo hi/lo (slot 5) with XOR swizzle
  {
    int row = t >> 1, half = t & 1;
    const __nv_bfloat16* sh = d_w_hi + 5 * (CDIM * CDIM) + (size_t)row * CDIM;
    const __nv_bfloat16* sl = d_w_lo + 5 * (CDIM * CDIM) + (size_t)row * CDIM;
    uint32_t dbase = sbase + KO_SW + (uint32_t)row * 256;
#pragma unroll
    for (int q = 0; q < 8; q++) {
      int k16 = half * 8 + q;
      uint32_t d = dbase + ((k16 ^ (row & 7)) * 16);
      CP_ASYNC16(d, (const char*)(sh + k16 * 8));
      CP_ASYNC16(d + KO_SW_BYTES, (const char*)(sl + k16 * 8));
    }
    CP_COMMIT();
  }

  // gather m[c][i][j0..j0+63] -> msf[jj][c]
#pragma unroll
  for (int q = 0; q < 16; q++) {
    int c = w + 8 * q;
    const float* src = d_mt + (size_t)c * NROWS + (size_t)i * LDIM + j0;
    msf[l * MSW + c] = src[l];
    msf[(l + 32) * MSW + c] = src[l + 32];
  }
  __syncthreads();

  // LN over c per jj row; emit bf16 hi/lo A tiles
  {
    float4 wv = *(const float4*)(lnw + l * 4);
    float4 bv = *(const float4*)(lnb + l * 4);
#pragma unroll
    for (int it = 0; it < 8; it++) {
      int jj = w + it * 8;
      const float* rowp = msf + jj * MSW + l * 4;
      float x0 = rowp[0], x1 = rowp[1], x2 = rowp[2], x3 = rowp[3];
      float mu = warp_sum(x0 + x1 + x2 + x3) * (1.f / CDIM);
      float d0 = x0 - mu, d1 = x1 - mu, d2 = x2 - mu, d3 = x3 - mu;
      float var = warp_sum(d0 * d0 + d1 * d1 + d2 * d2 + d3 * d3) * (1.f / CDIM);
      float rstd = rsqrtf(var + EPSV);
      float o0 = d0 * rstd * wv.x + bv.x, o1 = d1 * rstd * wv.y + bv.y;
      float o2 = d2 * rstd * wv.z + bv.z, o3 = d3 * rstd * wv.w + bv.w;
      float h0 = __bfloat162float(__float2bfloat16(o0));
      float h1 = __bfloat162float(__float2bfloat16(o1));
      float h2 = __bfloat162float(__float2bfloat16(o2));
      float h3 = __bfloat162float(__float2bfloat16(o3));
      uint32_t off = KO_SA + jj * 256 + (((l >> 1) ^ (jj & 7)) * 16) + (l & 1) * 8;
      *(uint2*)(smem + off) = make_uint2(pack2(h0, h1), pack2(h2, h3));
      *(uint2*)(smem + off + KO_SA_BYTES) =
          make_uint2(pack2(o0 - h0, o1 - h1), pack2(o2 - h2, o3 - h3));
    }
  }
  CP_WAIT(0);
  __syncthreads();

  // MMA: M=64 (jj), N=128 (out ch), K=128 (c); 2(M)x4(N) warps
  const int a_r = l & 15, a_c = l >> 4;
  const int b_r = (l & 7) + ((l >> 4) << 3), b_c = (l >> 3) & 1;
  const int wm = w & 1, wn = w >> 1;

  float acc[2][4][4];
#pragma unroll
  for (int mt = 0; mt < 2; mt++)
#pragma unroll
    for (int nt = 0; nt < 4; nt++)
#pragma unroll
      for (int q = 0; q < 4; q++) acc[mt][nt][q] = 0.f;

#pragma unroll
  for (int e = 0; e < 8; e++) {
    uint32_t ah[2][4], al[2][4], bh[2][4], bl[2][4];
#pragma unroll
    for (int mt = 0; mt < 2; mt++) {
      int row = wm * 32 + mt * 16 + a_r;
      uint32_t addr = sbase + KO_SA + row * 256 + (((e * 2 + a_c) ^ (row & 7)) * 16);
      LDSM_X4(ah[mt][0], ah[mt][1], ah[mt][2], ah[mt][3], addr);
      LDSM_X4(al[mt][0], al[mt][1], al[mt][2], al[mt][3], addr + KO_SA_BYTES);
    }
#pragma unroll
    for (int np = 0; np < 2; np++) {
      int row = wn * 32 + np * 16 + b_r;
      uint32_t addr = sbase + KO_SW + row * 256 + (((e * 2 + b_c) ^ (row & 7)) * 16);
      LDSM_X4(bh[np][0], bh[np][1], bh[np][2], bh[np][3], addr);
      LDSM_X4(bl[np][0], bl[np][1], bl[np][2], bl[np][3], addr + KO_SW_BYTES);
    }
#pragma unroll
    for (int mt = 0; mt < 2; mt++)
#pragma unroll
      for (int nt = 0; nt < 4; nt++) {
        uint32_t h0 = (nt & 1) ? bh[nt >> 1][2] : bh[nt >> 1][0];
        uint32_t h1 = (nt & 1) ? bh[nt >> 1][3] : bh[nt >> 1][1];
        uint32_t l0 = (nt & 1) ? bl[nt >> 1][2] : bl[nt >> 1][0];
        uint32_t l1 = (nt & 1) ? bl[nt >> 1][3] : bl[nt >> 1][1];
        MMA16816(acc[mt][nt], ah[mt], h0, h1);
        MMA16816(acc[mt][nt], al[mt], h0, h1);
        MMA16816(acc[mt][nt], ah[mt], l0, l1);
      }
  }

  // epilogue: out[n][ch] = acc * g * mask
#pragma unroll
  for (int mt = 0; mt < 2; mt++) {
#pragma unroll
    for (int h = 0; h < 2; h++) {
      int jj = wm * 32 + mt * 16 + (l >> 2) + 8 * h;
      size_t n = (size_t)i * LDIM + j0 + jj;
      float mkv = (float)mask[n];
      float* dst = out + n * CDIM + wn * 32 + 2 * (l & 3);
      const float* gsrc = d_g + n * CDIM + wn * 32 + 2 * (l & 3);
#pragma unroll
      for (int nt = 0; nt < 4; nt++) {
        float2 g2 = *(const float2*)(gsrc + nt * 8);
        float2 o = make_float2(acc[mt][nt][2 * h] * g2.x * mkv,
                               acc[mt][nt][2 * h + 1] * g2.y * mkv);
        *(float2*)(dst + nt * 8) = o;
      }
    }
  }
}

// ---------------- launch ----------------------------------------------------
extern "C" void kernel_launch(void* const* d_in, const int* in_sizes, int n_in,
                              void* d_out, int out_size) {
  const float* z        = (const float*)d_in[0];
  const int*   mask     = (const int*)  d_in[1];
  const float* ln_in_w  = (const float*)d_in[2];
  const float* ln_in_b  = (const float*)d_in[3];
  const float* ln_out_w = (const float*)d_in[4];
  const float* ln_out_b = (const float*)d_in[5];
  const float* Wpa = (const float*)d_in[6];
  const float* Wga = (const float*)d_in[7];
  const float* Wpb = (const float*)d_in[8];
  const float* Wgb = (const float*)d_in[9];
  const float* Wgo = (const float*)d_in[10];
  const float* Wpo = (const float*)d_in[11];
  float* out = (float*)d_out;

  cudaFuncSetAttribute(k_projmma, cudaFuncAttributeMaxDynamicSharedMemorySize, PROJ_SMEM);
  cudaFuncSetAttribute(k_einsum_mma, cudaFuncAttributeMaxDynamicSharedMemorySize, EIN_SMEM);
  cudaFuncSetAttribute(k_outmma, cudaFuncAttributeMaxDynamicSharedMemorySize, KO_SMEM);

  k_prew<<<dim3(8, 6), 256>>>(Wga, Wpa, Wgb, Wpb, Wgo, Wpo);
  k_projmma<<<NROWS / 64, 256, PROJ_SMEM>>>(z, mask, ln_in_w, ln_in_b);
  dim3 g2(LDIM / 128, LDIM / 128, CDIM);
  k_einsum_mma<<<g2, 256, EIN_SMEM>>>();
  dim3 g3(LDIM / 64, LDIM);
  k_outmma<<<g3, 256, KO_SMEM>>>(ln_out_w, ln_out_b, mask, out);
}

// round 12
// speedup vs baseline: 2.7641x; 1.3584x over previous
#include <cuda_runtime.h>
#include <cuda_bf16.h>
#include <cuda_fp16.h>
#include <cstdint>

#define LDIM 512
#define CDIM 128
#define NROWS (LDIM * LDIM)   // 262144 pair rows
#define EPSV 1e-5f

// ---------------- scratch (static device memory; no runtime allocation) ----
__device__ float d_g  [(size_t)NROWS * CDIM];      // sigmoid(zln @ W_gate_out), [n][c]
__device__ __half d_a_hi[(size_t)CDIM * NROWS];    // a split: [c][i][k]  (fp16)
__device__ __half d_a_lo[(size_t)CDIM * NROWS];
__device__ __half d_b_hi[(size_t)CDIM * NROWS];    // b hi only: [c][j][k]
__device__ float d_mt [(size_t)CDIM * NROWS];      // einsum result: [c][i][j]
// pre-transposed weights [w][ch][k] fp16; slots: Wga,Wpa,Wgb,Wpb,Wgo,Wpo
__device__ __half d_w16[6 * CDIM * CDIM];

// ---------------- arch-generic PTX helpers (plain sm_103 target!) ----------
__device__ __forceinline__ uint32_t smem_u32(const void* p) {
  uint32_t a;
  asm("{ .reg .u64 t; cvta.to.shared.u64 t, %1; cvt.u32.u64 %0, t; }" : "=r"(a) : "l"(p));
  return a;
}
#define CP_ASYNC16(s, g) \
  asm volatile("cp.async.cg.shared.global [%0], [%1], 16;" :: "r"(s), "l"(g) : "memory")
#define CP_COMMIT() asm volatile("cp.async.commit_group;" ::: "memory")
#define CP_WAIT(n)  asm volatile("cp.async.wait_group %0;" :: "n"(n) : "memory")

#define LDSM_X4(r0, r1, r2, r3, addr) \
  asm volatile("ldmatrix.sync.aligned.m8n8.x4.shared.b16 {%0,%1,%2,%3}, [%4];" \
    : "=r"(r0), "=r"(r1), "=r"(r2), "=r"(r3) : "r"(addr))

#define MMAH16816(d, a, b0, b1) \
  asm volatile("mma.sync.aligned.m16n8k16.row.col.f32.f16.f16.f32 " \
    "{%0,%1,%2,%3}, {%4,%5,%6,%7}, {%8,%9}, {%0,%1,%2,%3};" \
    : "+f"((d)[0]), "+f"((d)[1]), "+f"((d)[2]), "+f"((d)[3]) \
    : "r"((a)[0]), "r"((a)[1]), "r"((a)[2]), "r"((a)[3]), "r"(b0), "r"(b1))

#define MOVMAT(d, s) \
  asm volatile("movmatrix.sync.aligned.m8n8.trans.b16 %0, %1;" : "=r"(d) : "r"(s))

__device__ __forceinline__ float warp_sum(float v) {
#pragma unroll
  for (int o = 16; o > 0; o >>= 1) v += __shfl_xor_sync(0xffffffffu, v, o);
  return v;
}
__device__ __forceinline__ float sigmoidf(float x) {
  return 1.f / (1.f + __expf(-x));
}
__device__ __forceinline__ unsigned pack2h(float a, float b) {
  __half2 t = __floats2half2_rn(a, b);
  return *(unsigned*)&t;
}

// ---------------- K_prew: W -> [ch][k] fp16, 6 weights ----------------------
__global__ __launch_bounds__(256) void k_prew(
    const float* __restrict__ Wga, const float* __restrict__ Wpa,
    const float* __restrict__ Wgb, const float* __restrict__ Wpb,
    const float* __restrict__ Wgo, const float* __restrict__ Wpo) {
  const float* srcs[6] = {Wga, Wpa, Wgb, Wpb, Wgo, Wpo};
  const float* W = srcs[blockIdx.y];
  int t = threadIdx.x;
  int ch = blockIdx.x * 16 + (t >> 4);
  int k0 = (t & 15) * 8;
  uint32_t r[4];
#pragma unroll
  for (int q = 0; q < 4; q++) {
    float v0 = W[(k0 + 2 * q) * CDIM + ch];
    float v1 = W[(k0 + 2 * q + 1) * CDIM + ch];
    r[q] = pack2h(v0, v1);
  }
  size_t off = (size_t)blockIdx.y * (CDIM * CDIM) + (size_t)ch * CDIM + k0;
  *(uint4*)(d_w16 + off) = make_uint4(r[0], r[1], r[2], r[3]);
}

// ---------------- K1: fused LN + 5-way projection, fp16 2-term --------------
// CTA: 64 pair rows, 2 CTAs/SM. A (zln fp16 hi/lo) K=128 resident, XOR swizzle.
// W chunks: {gate, proj} fp16 per 16-k chunk, 3 buffers, pitch 48 B.
#define APITCH 256
#define SA_BYTES (64 * APITCH)      // 16 KB per A array
#define WPITCH 48                   // 32B data + 16B pad
#define SW_ARR (128 * WPITCH)       // 6144 B per W array chunk
#define SW_BUF (2 * SW_ARR)         // 12288 B per buffer
#define PROJ_SMEM (2 * SA_BYTES + 3 * SW_BUF)   // 69632 B

__device__ __forceinline__ void proj_issue_chunk(int ph, int t, uint32_t sW) {
  int s = ph >> 3, e = ph & 7;
  int arr = t >> 7;           // 0: gate weight, 1: proj weight
  int ch = t & 127;
  if (s < 2 || arr == 0) {
    int widx = s * 2 + arr;   // s=2,arr=0 -> Wgo
    const char* g = (const char*)(d_w16 + (size_t)widx * (CDIM * CDIM) +
                                  (size_t)ch * CDIM + e * 16);
    uint32_t d = sW + (ph % 3) * SW_BUF + arr * SW_ARR + ch * WPITCH;
    CP_ASYNC16(d, g);
    CP_ASYNC16(d + 16, g + 16);
  }
  CP_COMMIT();
}

__global__ __launch_bounds__(256, 2) void k_projmma(
    const float* __restrict__ z, const int* __restrict__ mask,
    const float* __restrict__ lnw, const float* __restrict__ lnb) {
  extern __shared__ char smem[];
  const uint32_t sbase = smem_u32(smem);
  const uint32_t sAhi = sbase, sW = sbase + 2 * SA_BYTES;
  const int n0 = blockIdx.x * 64;
  const int t = threadIdx.x, l = t & 31, w = t >> 5;

  proj_issue_chunk(0, t, sW);
  proj_issue_chunk(1, t, sW);

  // ---- LN: 64 rows, fp16 hi/lo into smem ----------------------------------
  {
    float4 wv = *(const float4*)(lnw + l * 4);
    float4 bv = *(const float4*)(lnb + l * 4);
#pragma unroll 4
    for (int it = 0; it < 8; it++) {
      int r = w + it * 8;
      float4 v = *(const float4*)(z + (size_t)(n0 + r) * CDIM + l * 4);
      float mu = warp_sum(v.x + v.y + v.z + v.w) * (1.f / CDIM);
      float dx = v.x - mu, dy = v.y - mu, dz = v.z - mu, dw = v.w - mu;
      float var = warp_sum(dx * dx + dy * dy + dz * dz + dw * dw) * (1.f / CDIM);
      float rstd = rsqrtf(var + EPSV);
      float o0 = dx * rstd * wv.x + bv.x, o1 = dy * rstd * wv.y + bv.y;
      float o2 = dz * rstd * wv.z + bv.z, o3 = dw * rstd * wv.w + bv.w;
      float h0 = __half2float(__float2half_rn(o0));
      float h1 = __half2float(__float2half_rn(o1));
      float h2 = __half2float(__float2half_rn(o2));
      float h3 = __half2float(__float2half_rn(o3));
      uint32_t off = r * APITCH + (((l >> 1) ^ (r & 7)) * 16) + (l & 1) * 8;
      *(uint2*)(smem + off) = make_uint2(pack2h(h0, h1), pack2h(h2, h3));
      *(uint2*)(smem + SA_BYTES + off) =
          make_uint2(pack2h(o0 - h0, o1 - h1), pack2h(o2 - h2, o3 - h3));
    }
  }
  __syncthreads();

  const int a_r = l & 15, a_c = l >> 4;
  const int b_r = (l & 7) + ((l >> 4) << 3), b_c = (l >> 3) & 1;
  const int wm = w & 1, wn = w >> 1;

  float mk[2][2];
#pragma unroll
  for (int mt = 0; mt < 2; mt++)
#pragma unroll
    for (int h = 0; h < 2; h++)
      mk[mt][h] = (float)mask[n0 + wm * 32 + mt * 16 + (l >> 2) + 8 * h];

  float accg[2][4][4], accp[2][4][4];

  for (int ph = 0; ph < 24; ph++) {
    const int s = ph >> 3, e = ph & 7;
    if (ph + 2 < 24) proj_issue_chunk(ph + 2, t, sW);
    if (ph < 22) { CP_WAIT(2); } else if (ph == 22) { CP_WAIT(1); } else { CP_WAIT(0); }
    __syncthreads();

    if (e == 0) {
#pragma unroll
      for (int mt = 0; mt < 2; mt++)
#pragma unroll
        for (int nt = 0; nt < 4; nt++)
#pragma unroll
          for (int q = 0; q < 4; q++) { accg[mt][nt][q] = 0.f; accp[mt][nt][q] = 0.f; }
    }

    const uint32_t wb = sW + (ph % 3) * SW_BUF;
    uint32_t ah[2][4], al[2][4];
#pragma unroll
    for (int mt = 0; mt < 2; mt++) {
      int row = wm * 32 + mt * 16 + a_r;
      uint32_t addr = sAhi + row * APITCH + (((e * 2 + a_c) ^ (row & 7)) * 16);
      LDSM_X4(ah[mt][0], ah[mt][1], ah[mt][2], ah[mt][3], addr);
      LDSM_X4(al[mt][0], al[mt][1], al[mt][2], al[mt][3], addr + SA_BYTES);
    }
#pragma unroll
    for (int gm = 0; gm < 2; gm++) {
      if (s == 2 && gm == 1) break;
      uint32_t bh[2][4];
      const uint32_t Bh = wb + gm * SW_ARR;
#pragma unroll
      for (int np = 0; np < 2; np++) {
        uint32_t caddr = (uint32_t)(wn * 32 + np * 16 + b_r) * WPITCH + b_c * 16;
        LDSM_X4(bh[np][0], bh[np][1], bh[np][2], bh[np][3], Bh + caddr);
      }
#pragma unroll
      for (int mt = 0; mt < 2; mt++) {
#pragma unroll
        for (int nt = 0; nt < 4; nt++) {
          uint32_t h0 = (nt & 1) ? bh[nt >> 1][2] : bh[nt >> 1][0];
          uint32_t h1 = (nt & 1) ? bh[nt >> 1][3] : bh[nt >> 1][1];
          float* acc = gm ? accp[mt][nt] : accg[mt][nt];
          MMAH16816(acc, ah[mt], h0, h1);
          MMAH16816(acc, al[mt], h0, h1);
        }
      }
    }

    if (e == 7) {
      if (s == 0) {                 // a: fp16 hi + lo
#pragma unroll
        for (int mt = 0; mt < 2; mt++) {
#pragma unroll
          for (int h = 0; h < 2; h++) {
            int nb = n0 + wm * 32 + mt * 16 + 8 * h + 2 * (l & 3);
#pragma unroll
            for (int nt = 0; nt < 4; nt++) {
              float v0 = sigmoidf(accg[mt][nt][2 * h]) * accp[mt][nt][2 * h] * mk[mt][h];
              float v1 = sigmoidf(accg[mt][nt][2 * h + 1]) * accp[mt][nt][2 * h + 1] * mk[mt][h];
              __half q0 = __float2half_rn(v0), q1 = __float2half_rn(v1);
              uint32_t hreg = ((uint32_t)__half_as_ushort(q1) << 16) | __half_as_ushort(q0);
              uint32_t lreg = pack2h(v0 - __half2float(q0), v1 - __half2float(q1));
              uint32_t ht, lt;
              MOVMAT(ht, hreg);
              MOVMAT(lt, lreg);
              size_t chrow = (size_t)(wn * 32 + nt * 8 + (l >> 2));
              *(uint32_t*)(d_a_hi + chrow * NROWS + nb) = ht;
              *(uint32_t*)(d_a_lo + chrow * NROWS + nb) = lt;
            }
          }
        }
      } else if (s == 1) {          // b: fp16 hi only
#pragma unroll
        for (int mt = 0; mt < 2; mt++) {
#pragma unroll
          for (int h = 0; h < 2; h++) {
            int nb = n0 + wm * 32 + mt * 16 + 8 * h + 2 * (l & 3);
#pragma unroll
            for (int nt = 0; nt < 4; nt++) {
              float v0 = sigmoidf(accg[mt][nt][2 * h]) * accp[mt][nt][2 * h] * mk[mt][h];
              float v1 = sigmoidf(accg[mt][nt][2 * h + 1]) * accp[mt][nt][2 * h + 1] * mk[mt][h];
              uint32_t hreg = pack2h(v0, v1);
              uint32_t ht;
              MOVMAT(ht, hreg);
              size_t chrow = (size_t)(wn * 32 + nt * 8 + (l >> 2));
              *(uint32_t*)(d_b_hi + chrow * NROWS + nb) = ht;
            }
          }
        }
      } else {                      // g
#pragma unroll
        for (int mt = 0; mt < 2; mt++) {
#pragma unroll
          for (int h = 0; h < 2; h++) {
            int n = n0 + wm * 32 + mt * 16 + (l >> 2) + 8 * h;
            float* dst = d_g + (size_t)n * CDIM + wn * 32 + 2 * (l & 3);
#pragma unroll
            for (int nt = 0; nt < 4; nt++) {
              float2 o = make_float2(sigmoidf(accg[mt][nt][2 * h]),
                                     sigmoidf(accg[mt][nt][2 * h + 1]));
              *(float2*)(dst + nt * 8) = o;
            }
          }
        }
      }
    }
    __syncthreads();
  }
}

// ---------------- K2: channel-batched einsum, fp16 2-term (unchanged) -------
#define EROWB 80
#define ARRB (128 * EROWB)
#define BUFB (3 * ARRB)             // 30720
#define EIN_SMEM (2 * BUFB)         // 61440

__global__ __launch_bounds__(256, 2) void k_einsum_mma() {
  extern __shared__ char smem[];
  const uint32_t sbase = smem_u32(smem);
  const int c = blockIdx.z;
  const int i0 = blockIdx.x * 128, j0 = blockIdx.y * 128;
  const int tid = threadIdx.x;
  const size_t coff = (size_t)c * NROWS;

  const int larr = tid >> 6;
  const bool tworow = larr < 2;
  const __half* lsrc;
  int lrow;
  uint32_t lsmem;
  if (tworow) {
    lsrc = (larr ? d_a_lo : d_a_hi) + coff + (size_t)i0 * LDIM;
    lrow = (tid & 63) * 2;
    lsmem = sbase + larr * ARRB + lrow * EROWB;
  } else {
    lsrc = d_b_hi + coff + (size_t)j0 * LDIM;
    lrow = (larr - 2) * 64 + (tid & 63);
    lsmem = sbase + 2 * ARRB + lrow * EROWB;
  }

#define ISSUE_LOAD(buf, kc) do { \
    const char* g0 = (const char*)(lsrc + (size_t)lrow * LDIM + (kc)); \
    uint32_t s0 = lsmem + (buf) * BUFB; \
    CP_ASYNC16(s0,      g0);      CP_ASYNC16(s0 + 16, g0 + 16); \
    CP_ASYNC16(s0 + 32, g0 + 32); CP_ASYNC16(s0 + 48, g0 + 48); \
    if (tworow) { \
      const char* g1 = (const char*)(lsrc + (size_t)(lrow + 1) * LDIM + (kc)); \
      uint32_t s1 = s0 + EROWB; \
      CP_ASYNC16(s1,      g1);      CP_ASYNC16(s1 + 16, g1 + 16); \
      CP_ASYNC16(s1 + 32, g1 + 32); CP_ASYNC16(s1 + 48, g1 + 48); \
    } \
    CP_COMMIT(); \
  } while (0)

  const int w = tid >> 5, l = tid & 31;
  const int wm = w & 1, wn = w >> 1;
  const int a_r = l & 15, a_c = l >> 4;
  const int b_r = (l & 7) + ((l >> 4) << 3);
  const int b_c = (l >> 3) & 1;

  float acc[4][4][4];
#pragma unroll
  for (int mt = 0; mt < 4; mt++)
#pragma unroll
    for (int nt = 0; nt < 4; nt++)
#pragma unroll
      for (int q = 0; q < 4; q++) acc[mt][nt][q] = 0.f;

  ISSUE_LOAD(0, 0);

  for (int ci = 0; ci < 16; ci++) {
    const int buf = ci & 1;
    if (ci < 15) ISSUE_LOAD(buf ^ 1, (ci + 1) * 32);
    if (ci < 15) { CP_WAIT(1); } else { CP_WAIT(0); }
    __syncthreads();

    const uint32_t bufbase = sbase + buf * BUFB;
#pragma unroll
    for (int ks = 0; ks < 2; ks++) {
      const uint32_t kof = ks * 32 + a_c * 16;
      const uint32_t kofb = ks * 32 + b_c * 16;
      uint32_t ah[4][4], alq[4][4], bh[2][4];
#pragma unroll
      for (int mt = 0; mt < 4; mt++) {
        uint32_t addr = bufbase + (uint32_t)(wm * 64 + mt * 16 + a_r) * EROWB + kof;
        LDSM_X4(ah[mt][0], ah[mt][1], ah[mt][2], ah[mt][3], addr);
        LDSM_X4(alq[mt][0], alq[mt][1], alq[mt][2], alq[mt][3], addr + ARRB);
      }
#pragma unroll
      for (int np = 0; np < 2; np++) {
        uint32_t addr = bufbase + 2 * ARRB + (uint32_t)(wn * 32 + np * 16 + b_r) * EROWB + kofb;
        LDSM_X4(bh[np][0], bh[np][1], bh[np][2], bh[np][3], addr);
      }
#pragma unroll
      for (int mt = 0; mt < 4; mt++)
#pragma unroll
        for (int nt = 0; nt < 4; nt++) {
          uint32_t b0 = (nt & 1) ? bh[nt >> 1][2] : bh[nt >> 1][0];
          uint32_t b1 = (nt & 1) ? bh[nt >> 1][3] : bh[nt >> 1][1];
          MMAH16816(acc[mt][nt], ah[mt], b0, b1);
          MMAH16816(acc[mt][nt], alq[mt], b0, b1);
        }
    }
    __syncthreads();
  }

  float* mbase = d_mt + coff;
#pragma unroll
  for (int mt = 0; mt < 4; mt++) {
#pragma unroll
    for (int h = 0; h < 2; h++) {
      int row = i0 + wm * 64 + mt * 16 + (l >> 2) + h * 8;
      float* rp = mbase + (size_t)row * LDIM + j0 + wn * 32 + (l & 3) * 2;
#pragma unroll
      for (int nt = 0; nt < 4; nt++) {
        float2 v = make_float2(acc[mt][nt][h * 2], acc[mt][nt][h * 2 + 1]);
        *(float2*)(rp + nt * 8) = v;
      }
    }
  }
#undef ISSUE_LOAD
}

// ---------------- K3: LN(m) + @W_proj_out, fp16 2-term, 2 CTAs/SM -----------
#define MSW 129
#define KO_MS_BYTES (64 * MSW * 4)                 // 33024
#define KO_SA (KO_MS_BYTES)
#define KO_SA_BYTES (64 * 256)                     // 16384 per array
#define KO_SW (KO_SA + 2 * KO_SA_BYTES)            // 65792
#define KO_SW_BYTES (128 * 256)                    // 32768 (hi only)
#define KO_SMEM (KO_SW + KO_SW_BYTES)              // 98560

__global__ __launch_bounds__(256, 2) void k_outmma(
    const float* __restrict__ lnw, const float* __restrict__ lnb,
    const int* __restrict__ mask, float* __restrict__ out) {
  extern __shared__ char smem[];
  const uint32_t sbase = smem_u32(smem);
  float* msf = (float*)smem;
  const int i = blockIdx.y;
  const int j0 = blockIdx.x * 64;
  const int t = threadIdx.x, l = t & 31, w = t >> 5;

  // stage Wpo fp16 (slot 5) with XOR swizzle
  {
    int row = t >> 1, half = t & 1;
    const __half* sh = d_w16 + 5 * (CDIM * CDIM) + (size_t)row * CDIM;
    uint32_t dbase = sbase + KO_SW + (uint32_t)row * 256;
#pragma unroll
    for (int q = 0; q < 8; q++) {
      int k16 = half * 8 + q;
      CP_ASYNC16(dbase + ((k16 ^ (row & 7)) * 16), (const char*)(sh + k16 * 8));
    }
    CP_COMMIT();
  }

  // gather m[c][i][j0..j0+63] -> msf[jj][c]
#pragma unroll
  for (int q = 0; q < 16; q++) {
    int c = w + 8 * q;
    const float* src = d_mt + (size_t)c * NROWS + (size_t)i * LDIM + j0;
    msf[l * MSW + c] = src[l];
    msf[(l + 32) * MSW + c] = src[l + 32];
  }
  __syncthreads();

  // LN over c per jj row; emit fp16 hi/lo A tiles
  {
    float4 wv = *(const float4*)(lnw + l * 4);
    float4 bv = *(const float4*)(lnb + l * 4);
#pragma unroll
    for (int it = 0; it < 8; it++) {
      int jj = w + it * 8;
      const float* rowp = msf + jj * MSW + l * 4;
      float x0 = rowp[0], x1 = rowp[1], x2 = rowp[2], x3 = rowp[3];
      float mu = warp_sum(x0 + x1 + x2 + x3) * (1.f / CDIM);
      float d0 = x0 - mu, d1 = x1 - mu, d2 = x2 - mu, d3 = x3 - mu;
      float var = warp_sum(d0 * d0 + d1 * d1 + d2 * d2 + d3 * d3) * (1.f / CDIM);
      float rstd = rsqrtf(var + EPSV);
      float o0 = d0 * rstd * wv.x + bv.x, o1 = d1 * rstd * wv.y + bv.y;
      float o2 = d2 * rstd * wv.z + bv.z, o3 = d3 * rstd * wv.w + bv.w;
      float h0 = __half2float(__float2half_rn(o0));
      float h1 = __half2float(__float2half_rn(o1));
      float h2 = __half2float(__float2half_rn(o2));
      float h3 = __half2float(__float2half_rn(o3));
      uint32_t off = KO_SA + jj * 256 + (((l >> 1) ^ (jj & 7)) * 16) + (l & 1) * 8;
      *(uint2*)(smem + off) = make_uint2(pack2h(h0, h1), pack2h(h2, h3));
      *(uint2*)(smem + off + KO_SA_BYTES) =
          make_uint2(pack2h(o0 - h0, o1 - h1), pack2h(o2 - h2, o3 - h3));
    }
  }
  CP_WAIT(0);
  __syncthreads();

  // MMA: M=64 (jj), N=128 (out ch), K=128 (c); 2(M)x4(N) warps, 2 terms
  const int a_r = l & 15, a_c = l >> 4;
  const int b_r = (l & 7) + ((l >> 4) << 3), b_c = (l >> 3) & 1;
  const int wm = w & 1, wn = w >> 1;

  float acc[2][4][4];
#pragma unroll
  for (int mt = 0; mt < 2; mt++)
#pragma unroll
    for (int nt = 0; nt < 4; nt++)
#pragma unroll
      for (int q = 0; q < 4; q++) acc[mt][nt][q] = 0.f;

#pragma unroll
  for (int e = 0; e < 8; e++) {
    uint32_t ah[2][4], al[2][4], bh[2][4];
#pragma unroll
    for (int mt = 0; mt < 2; mt++) {
      int row = wm * 32 + mt * 16 + a_r;
      uint32_t addr = sbase + KO_SA + row * 256 + (((e * 2 + a_c) ^ (row & 7)) * 16);
      LDSM_X4(ah[mt][0], ah[mt][1], ah[mt][2], ah[mt][3], addr);
      LDSM_X4(al[mt][0], al[mt][1], al[mt][2], al[mt][3], addr + KO_SA_BYTES);
    }
#pragma unroll
    for (int np = 0; np < 2; np++) {
      int row = wn * 32 + np * 16 + b_r;
      uint32_t addr = sbase + KO_SW + row * 256 + (((e * 2 + b_c) ^ (row & 7)) * 16);
      LDSM_X4(bh[np][0], bh[np][1], bh[np][2], bh[np][3], addr);
    }
#pragma unroll
    for (int mt = 0; mt < 2; mt++)
#pragma unroll
      for (int nt = 0; nt < 4; nt++) {
        uint32_t h0 = (nt & 1) ? bh[nt >> 1][2] : bh[nt >> 1][0];
        uint32_t h1 = (nt & 1) ? bh[nt >> 1][3] : bh[nt >> 1][1];
        MMAH16816(acc[mt][nt], ah[mt], h0, h1);
        MMAH16816(acc[mt][nt], al[mt], h0, h1);
      }
  }

  // epilogue: out[n][ch] = acc * g * mask
#pragma unroll
  for (int mt = 0; mt < 2; mt++) {
#pragma unroll
    for (int h = 0; h < 2; h++) {
      int jj = wm * 32 + mt * 16 + (l >> 2) + 8 * h;
      size_t n = (size_t)i * LDIM + j0 + jj;
      float mkv = (float)mask[n];
      float* dst = out + n * CDIM + wn * 32 + 2 * (l & 3);
      const float* gsrc = d_g + n * CDIM + wn * 32 + 2 * (l & 3);
#pragma unroll
      for (int nt = 0; nt < 4; nt++) {
        float2 g2 = *(const float2*)(gsrc + nt * 8);
        float2 o = make_float2(acc[mt][nt][2 * h] * g2.x * mkv,
                               acc[mt][nt][2 * h + 1] * g2.y * mkv);
        *(float2*)(dst + nt * 8) = o;
      }
    }
  }
}

// ---------------- launch ----------------------------------------------------
extern "C" void kernel_launch(void* const* d_in, const int* in_sizes, int n_in,
                              void* d_out, int out_size) {
  const float* z        = (const float*)d_in[0];
  const int*   mask     = (const int*)  d_in[1];
  const float* ln_in_w  = (const float*)d_in[2];
  const float* ln_in_b  = (const float*)d_in[3];
  const float* ln_out_w = (const float*)d_in[4];
  const float* ln_out_b = (const float*)d_in[5];
  const float* Wpa = (const float*)d_in[6];
  const float* Wga = (const float*)d_in[7];
  const float* Wpb = (const float*)d_in[8];
  const float* Wgb = (const float*)d_in[9];
  const float* Wgo = (const float*)d_in[10];
  const float* Wpo = (const float*)d_in[11];
  float* out = (float*)d_out;

  cudaFuncSetAttribute(k_projmma, cudaFuncAttributeMaxDynamicSharedMemorySize, PROJ_SMEM);
  cudaFuncSetAttribute(k_einsum_mma, cudaFuncAttributeMaxDynamicSharedMemorySize, EIN_SMEM);
  cudaFuncSetAttribute(k_outmma, cudaFuncAttributeMaxDynamicSharedMemorySize, KO_SMEM);

  k_prew<<<dim3(8, 6), 256>>>(Wga, Wpa, Wgb, Wpb, Wgo, Wpo);
  k_projmma<<<NROWS / 64, 256, PROJ_SMEM>>>(z, mask, ln_in_w, ln_in_b);
  dim3 g2(LDIM / 128, LDIM / 128, CDIM);
  k_einsum_mma<<<g2, 256, EIN_SMEM>>>();
  dim3 g3(LDIM / 64, LDIM);
  k_outmma<<<g3, 256, KO_SMEM>>>(ln_out_w, ln_out_b, mask, out);
}

// round 13
// speedup vs baseline: 3.3278x; 1.2040x over previous
#include <cuda_runtime.h>
#include <cuda_bf16.h>
#include <cuda_fp16.h>
#include <cstdint>

#define LDIM 512
#define CDIM 128
#define NROWS (LDIM * LDIM)   // 262144 pair rows
#define EPSV 1e-5f

// ---------------- scratch (static device memory; no runtime allocation) ----
__device__ float d_g  [(size_t)NROWS * CDIM];      // sigmoid(zln @ W_gate_out), [n][c]
__device__ __half d_a16[(size_t)CDIM * NROWS];     // a fp16: [c][i][k]
__device__ __half d_b16[(size_t)CDIM * NROWS];     // b fp16: [c][j][k]
__device__ float d_mt [(size_t)CDIM * NROWS];      // einsum result: [c][i][j]
// pre-transposed weights [w][ch][k] fp16; slots: Wga,Wpa,Wgb,Wpb,Wgo,Wpo
__device__ __half d_w16[6 * CDIM * CDIM];

// ---------------- arch-generic PTX helpers (plain sm_103 target!) ----------
__device__ __forceinline__ uint32_t smem_u32(const void* p) {
  uint32_t a;
  asm("{ .reg .u64 t; cvta.to.shared.u64 t, %1; cvt.u32.u64 %0, t; }" : "=r"(a) : "l"(p));
  return a;
}
#define CP_ASYNC16(s, g) \
  asm volatile("cp.async.cg.shared.global [%0], [%1], 16;" :: "r"(s), "l"(g) : "memory")
#define CP_COMMIT() asm volatile("cp.async.commit_group;" ::: "memory")
#define CP_WAIT(n)  asm volatile("cp.async.wait_group %0;" :: "n"(n) : "memory")

#define LDSM_X4(r0, r1, r2, r3, addr) \
  asm volatile("ldmatrix.sync.aligned.m8n8.x4.shared.b16 {%0,%1,%2,%3}, [%4];" \
    : "=r"(r0), "=r"(r1), "=r"(r2), "=r"(r3) : "r"(addr))

#define MMAH16816(d, a, b0, b1) \
  asm volatile("mma.sync.aligned.m16n8k16.row.col.f32.f16.f16.f32 " \
    "{%0,%1,%2,%3}, {%4,%5,%6,%7}, {%8,%9}, {%0,%1,%2,%3};" \
    : "+f"((d)[0]), "+f"((d)[1]), "+f"((d)[2]), "+f"((d)[3]) \
    : "r"((a)[0]), "r"((a)[1]), "r"((a)[2]), "r"((a)[3]), "r"(b0), "r"(b1))

#define MOVMAT(d, s) \
  asm volatile("movmatrix.sync.aligned.m8n8.trans.b16 %0, %1;" : "=r"(d) : "r"(s))

__device__ __forceinline__ float warp_sum(float v) {
#pragma unroll
  for (int o = 16; o > 0; o >>= 1) v += __shfl_xor_sync(0xffffffffu, v, o);
  return v;
}
__device__ __forceinline__ float sigmoidf(float x) {
  return 1.f / (1.f + __expf(-x));
}
__device__ __forceinline__ unsigned pack2h(float a, float b) {
  __half2 t = __floats2half2_rn(a, b);
  return *(unsigned*)&t;
}

// ---------------- K_prew: W -> [ch][k] fp16, 6 weights ----------------------
__global__ __launch_bounds__(256) void k_prew(
    const float* __restrict__ Wga, const float* __restrict__ Wpa,
    const float* __restrict__ Wgb, const float* __restrict__ Wpb,
    const float* __restrict__ Wgo, const float* __restrict__ Wpo) {
  const float* srcs[6] = {Wga, Wpa, Wgb, Wpb, Wgo, Wpo};
  const float* W = srcs[blockIdx.y];
  int t = threadIdx.x;
  int ch = blockIdx.x * 16 + (t >> 4);
  int k0 = (t & 15) * 8;
  uint32_t r[4];
#pragma unroll
  for (int q = 0; q < 4; q++) {
    float v0 = W[(k0 + 2 * q) * CDIM + ch];
    float v1 = W[(k0 + 2 * q + 1) * CDIM + ch];
    r[q] = pack2h(v0, v1);
  }
  size_t off = (size_t)blockIdx.y * (CDIM * CDIM) + (size_t)ch * CDIM + k0;
  *(uint4*)(d_w16 + off) = make_uint4(r[0], r[1], r[2], r[3]);
}

// ---------------- K1: fused LN + 5-way projection, fp16 2-term --------------
// CTA: 64 pair rows, 2 CTAs/SM. A (zln fp16 hi/lo) K=128 resident, XOR swizzle.
// W chunks: {gate, proj} fp16 per 16-k chunk, 3 buffers, pitch 48 B.
#define APITCH 256
#define SA_BYTES (64 * APITCH)      // 16 KB per A array
#define WPITCH 48                   // 32B data + 16B pad
#define SW_ARR (128 * WPITCH)       // 6144 B per W array chunk
#define SW_BUF (2 * SW_ARR)         // 12288 B per buffer
#define PROJ_SMEM (2 * SA_BYTES + 3 * SW_BUF)   // 69632 B

__device__ __forceinline__ void proj_issue_chunk(int ph, int t, uint32_t sW) {
  int s = ph >> 3, e = ph & 7;
  int arr = t >> 7;           // 0: gate weight, 1: proj weight
  int ch = t & 127;
  if (s < 2 || arr == 0) {
    int widx = s * 2 + arr;   // s=2,arr=0 -> Wgo
    const char* g = (const char*)(d_w16 + (size_t)widx * (CDIM * CDIM) +
                                  (size_t)ch * CDIM + e * 16);
    uint32_t d = sW + (ph % 3) * SW_BUF + arr * SW_ARR + ch * WPITCH;
    CP_ASYNC16(d, g);
    CP_ASYNC16(d + 16, g + 16);
  }
  CP_COMMIT();
}

__global__ __launch_bounds__(256, 2) void k_projmma(
    const float* __restrict__ z, const int* __restrict__ mask,
    const float* __restrict__ lnw, const float* __restrict__ lnb) {
  extern __shared__ char smem[];
  const uint32_t sbase = smem_u32(smem);
  const uint32_t sAhi = sbase, sW = sbase + 2 * SA_BYTES;
  const int n0 = blockIdx.x * 64;
  const int t = threadIdx.x, l = t & 31, w = t >> 5;

  proj_issue_chunk(0, t, sW);
  proj_issue_chunk(1, t, sW);

  // ---- LN: 64 rows, fp16 hi/lo into smem ----------------------------------
  {
    float4 wv = *(const float4*)(lnw + l * 4);
    float4 bv = *(const float4*)(lnb + l * 4);
#pragma unroll 4
    for (int it = 0; it < 8; it++) {
      int r = w + it * 8;
      float4 v = *(const float4*)(z + (size_t)(n0 + r) * CDIM + l * 4);
      float mu = warp_sum(v.x + v.y + v.z + v.w) * (1.f / CDIM);
      float dx = v.x - mu, dy = v.y - mu, dz = v.z - mu, dw = v.w - mu;
      float var = warp_sum(dx * dx + dy * dy + dz * dz + dw * dw) * (1.f / CDIM);
      float rstd = rsqrtf(var + EPSV);
      float o0 = dx * rstd * wv.x + bv.x, o1 = dy * rstd * wv.y + bv.y;
      float o2 = dz * rstd * wv.z + bv.z, o3 = dw * rstd * wv.w + bv.w;
      float h0 = __half2float(__float2half_rn(o0));
      float h1 = __half2float(__float2half_rn(o1));
      float h2 = __half2float(__float2half_rn(o2));
      float h3 = __half2float(__float2half_rn(o3));
      uint32_t off = r * APITCH + (((l >> 1) ^ (r & 7)) * 16) + (l & 1) * 8;
      *(uint2*)(smem + off) = make_uint2(pack2h(h0, h1), pack2h(h2, h3));
      *(uint2*)(smem + SA_BYTES + off) =
          make_uint2(pack2h(o0 - h0, o1 - h1), pack2h(o2 - h2, o3 - h3));
    }
  }
  __syncthreads();

  const int a_r = l & 15, a_c = l >> 4;
  const int b_r = (l & 7) + ((l >> 4) << 3), b_c = (l >> 3) & 1;
  const int wm = w & 1, wn = w >> 1;

  float mk[2][2];
#pragma unroll
  for (int mt = 0; mt < 2; mt++)
#pragma unroll
    for (int h = 0; h < 2; h++)
      mk[mt][h] = (float)mask[n0 + wm * 32 + mt * 16 + (l >> 2) + 8 * h];

  float accg[2][4][4], accp[2][4][4];

  for (int ph = 0; ph < 24; ph++) {
    const int s = ph >> 3, e = ph & 7;
    if (ph + 2 < 24) proj_issue_chunk(ph + 2, t, sW);
    if (ph < 22) { CP_WAIT(2); } else if (ph == 22) { CP_WAIT(1); } else { CP_WAIT(0); }
    __syncthreads();

    if (e == 0) {
#pragma unroll
      for (int mt = 0; mt < 2; mt++)
#pragma unroll
        for (int nt = 0; nt < 4; nt++)
#pragma unroll
          for (int q = 0; q < 4; q++) { accg[mt][nt][q] = 0.f; accp[mt][nt][q] = 0.f; }
    }

    const uint32_t wb = sW + (ph % 3) * SW_BUF;
    uint32_t ah[2][4], al[2][4];
#pragma unroll
    for (int mt = 0; mt < 2; mt++) {
      int row = wm * 32 + mt * 16 + a_r;
      uint32_t addr = sAhi + row * APITCH + (((e * 2 + a_c) ^ (row & 7)) * 16);
      LDSM_X4(ah[mt][0], ah[mt][1], ah[mt][2], ah[mt][3], addr);
      LDSM_X4(al[mt][0], al[mt][1], al[mt][2], al[mt][3], addr + SA_BYTES);
    }
#pragma unroll
    for (int gm = 0; gm < 2; gm++) {
      if (s == 2 && gm == 1) break;
      uint32_t bh[2][4];
      const uint32_t Bh = wb + gm * SW_ARR;
#pragma unroll
      for (int np = 0; np < 2; np++) {
        uint32_t caddr = (uint32_t)(wn * 32 + np * 16 + b_r) * WPITCH + b_c * 16;
        LDSM_X4(bh[np][0], bh[np][1], bh[np][2], bh[np][3], Bh + caddr);
      }
#pragma unroll
      for (int mt = 0; mt < 2; mt++) {
#pragma unroll
        for (int nt = 0; nt < 4; nt++) {
          uint32_t h0 = (nt & 1) ? bh[nt >> 1][2] : bh[nt >> 1][0];
          uint32_t h1 = (nt & 1) ? bh[nt >> 1][3] : bh[nt >> 1][1];
          float* acc = gm ? accp[mt][nt] : accg[mt][nt];
          MMAH16816(acc, ah[mt], h0, h1);
          MMAH16816(acc, al[mt], h0, h1);
        }
      }
    }

    if (e == 7) {
      if (s < 2) {                  // a or b: fp16 value, transposed store
        __half* dst16 = s ? d_b16 : d_a16;
#pragma unroll
        for (int mt = 0; mt < 2; mt++) {
#pragma unroll
          for (int h = 0; h < 2; h++) {
            int nb = n0 + wm * 32 + mt * 16 + 8 * h + 2 * (l & 3);
#pragma unroll
            for (int nt = 0; nt < 4; nt++) {
              float v0 = sigmoidf(accg[mt][nt][2 * h]) * accp[mt][nt][2 * h] * mk[mt][h];
              float v1 = sigmoidf(accg[mt][nt][2 * h + 1]) * accp[mt][nt][2 * h + 1] * mk[mt][h];
              uint32_t hreg = pack2h(v0, v1);
              uint32_t ht;
              MOVMAT(ht, hreg);
              size_t chrow = (size_t)(wn * 32 + nt * 8 + (l >> 2));
              *(uint32_t*)(dst16 + chrow * NROWS + nb) = ht;
            }
          }
        }
      } else {                      // g
#pragma unroll
        for (int mt = 0; mt < 2; mt++) {
#pragma unroll
          for (int h = 0; h < 2; h++) {
            int n = n0 + wm * 32 + mt * 16 + (l >> 2) + 8 * h;
            float* dst = d_g + (size_t)n * CDIM + wn * 32 + 2 * (l & 3);
#pragma unroll
            for (int nt = 0; nt < 4; nt++) {
              float2 o = make_float2(sigmoidf(accg[mt][nt][2 * h]),
                                     sigmoidf(accg[mt][nt][2 * h + 1]));
              *(float2*)(dst + nt * 8) = o;
            }
          }
        }
      }
    }
    __syncthreads();
  }
}

// ---------------- K2: channel-batched einsum, fp16 1-term, 3-stage ----------
#define EROWB 80
#define ARRB (128 * EROWB)          // 10240 per array
#define STAGEB (2 * ARRB)           // 20480 per stage (a tile + b tile)
#define EIN_SMEM (3 * STAGEB)       // 61440

__global__ __launch_bounds__(256, 2) void k_einsum_mma() {
  extern __shared__ char smem[];
  const uint32_t sbase = smem_u32(smem);
  const int c = blockIdx.z;
  const int i0 = blockIdx.x * 128, j0 = blockIdx.y * 128;
  const int tid = threadIdx.x;
  const size_t coff = (size_t)c * NROWS;

  // loader: 256 threads = 2 arrays x 128 rows, one 64B row-chunk each
  const int larr = tid >> 7;            // 0: a tile (i rows), 1: b tile (j rows)
  const int lrow = tid & 127;
  const __half* lsrc = (larr ? d_b16 + coff + (size_t)(j0 + lrow) * LDIM
                             : d_a16 + coff + (size_t)(i0 + lrow) * LDIM);
  const uint32_t lsmem = sbase + larr * ARRB + lrow * EROWB;

#define ISSUE_LOAD(stage, kc) do { \
    const char* g0 = (const char*)(lsrc + (kc)); \
    uint32_t s0 = lsmem + (stage) * STAGEB; \
    CP_ASYNC16(s0,      g0);      CP_ASYNC16(s0 + 16, g0 + 16); \
    CP_ASYNC16(s0 + 32, g0 + 32); CP_ASYNC16(s0 + 48, g0 + 48); \
    CP_COMMIT(); \
  } while (0)

  const int w = tid >> 5, l = tid & 31;
  const int wm = w & 1, wn = w >> 1;
  const int a_r = l & 15, a_c = l >> 4;
  const int b_r = (l & 7) + ((l >> 4) << 3);
  const int b_c = (l >> 3) & 1;

  float acc[4][4][4];
#pragma unroll
  for (int mt = 0; mt < 4; mt++)
#pragma unroll
    for (int nt = 0; nt < 4; nt++)
#pragma unroll
      for (int q = 0; q < 4; q++) acc[mt][nt][q] = 0.f;

  ISSUE_LOAD(0, 0);
  ISSUE_LOAD(1, 32);

  for (int ci = 0; ci < 16; ci++) {
    const int stage = ci % 3;
    if (ci < 14) { ISSUE_LOAD((ci + 2) % 3, (ci + 2) * 32); CP_WAIT(2); }
    else if (ci == 14) { CP_WAIT(1); } else { CP_WAIT(0); }
    __syncthreads();

    const uint32_t bufbase = sbase + stage * STAGEB;
#pragma unroll
    for (int ks = 0; ks < 2; ks++) {
      const uint32_t kof = ks * 32 + a_c * 16;
      const uint32_t kofb = ks * 32 + b_c * 16;
      uint32_t ah[4][4], bh[2][4];
#pragma unroll
      for (int mt = 0; mt < 4; mt++) {
        uint32_t addr = bufbase + (uint32_t)(wm * 64 + mt * 16 + a_r) * EROWB + kof;
        LDSM_X4(ah[mt][0], ah[mt][1], ah[mt][2], ah[mt][3], addr);
      }
#pragma unroll
      for (int np = 0; np < 2; np++) {
        uint32_t addr = bufbase + ARRB + (uint32_t)(wn * 32 + np * 16 + b_r) * EROWB + kofb;
        LDSM_X4(bh[np][0], bh[np][1], bh[np][2], bh[np][3], addr);
      }
#pragma unroll
      for (int mt = 0; mt < 4; mt++)
#pragma unroll
        for (int nt = 0; nt < 4; nt++) {
          uint32_t b0 = (nt & 1) ? bh[nt >> 1][2] : bh[nt >> 1][0];
          uint32_t b1 = (nt & 1) ? bh[nt >> 1][3] : bh[nt >> 1][1];
          MMAH16816(acc[mt][nt], ah[mt], b0, b1);
        }
    }
    __syncthreads();
  }

  float* mbase = d_mt + coff;
#pragma unroll
  for (int mt = 0; mt < 4; mt++) {
#pragma unroll
    for (int h = 0; h < 2; h++) {
      int row = i0 + wm * 64 + mt * 16 + (l >> 2) + h * 8;
      float* rp = mbase + (size_t)row * LDIM + j0 + wn * 32 + (l & 3) * 2;
#pragma unroll
      for (int nt = 0; nt < 4; nt++) {
        float2 v = make_float2(acc[mt][nt][h * 2], acc[mt][nt][h * 2 + 1]);
        *(float2*)(rp + nt * 8) = v;
      }
    }
  }
#undef ISSUE_LOAD
}

// ---------------- K3: LN(m) + @W_proj_out, fp16 2-term, 2 CTAs/SM -----------
#define MSW 129
#define KO_MS_BYTES (64 * MSW * 4)                 // 33024
#define KO_SA (KO_MS_BYTES)
#define KO_SA_BYTES (64 * 256)                     // 16384 per array
#define KO_SW (KO_SA + 2 * KO_SA_BYTES)            // 65792
#define KO_SW_BYTES (128 * 256)                    // 32768 (hi only)
#define KO_SMEM (KO_SW + KO_SW_BYTES)              // 98560

__global__ __launch_bounds__(256, 2) void k_outmma(
    const float* __restrict__ lnw, const float* __restrict__ lnb,
    const int* __restrict__ mask, float* __restrict__ out) {
  extern __shared__ char smem[];
  const uint32_t sbase = smem_u32(smem);
  float* msf = (float*)smem;
  const int i = blockIdx.y;
  const int j0 = blockIdx.x * 64;
  const int t = threadIdx.x, l = t & 31, w = t >> 5;

  // stage Wpo fp16 (slot 5) with XOR swizzle
  {
    int row = t >> 1, half = t & 1;
    const __half* sh = d_w16 + 5 * (CDIM * CDIM) + (size_t)row * CDIM;
    uint32_t dbase = sbase + KO_SW + (uint32_t)row * 256;
#pragma unroll
    for (int q = 0; q < 8; q++) {
      int k16 = half * 8 + q;
      CP_ASYNC16(dbase + ((k16 ^ (row & 7)) * 16), (const char*)(sh + k16 * 8));
    }
    CP_COMMIT();
  }

  // gather m[c][i][j0..j0+63] -> msf[jj][c]
#pragma unroll
  for (int q = 0; q < 16; q++) {
    int c = w + 8 * q;
    const float* src = d_mt + (size_t)c * NROWS + (size_t)i * LDIM + j0;
    msf[l * MSW + c] = src[l];
    msf[(l + 32) * MSW + c] = src[l + 32];
  }
  __syncthreads();

  // LN over c per jj row; emit fp16 hi/lo A tiles
  {
    float4 wv = *(const float4*)(lnw + l * 4);
    float4 bv = *(const float4*)(lnb + l * 4);
#pragma unroll
    for (int it = 0; it < 8; it++) {
      int jj = w + it * 8;
      const float* rowp = msf + jj * MSW + l * 4;
      float x0 = rowp[0], x1 = rowp[1], x2 = rowp[2], x3 = rowp[3];
      float mu = warp_sum(x0 + x1 + x2 + x3) * (1.f / CDIM);
      float d0 = x0 - mu, d1 = x1 - mu, d2 = x2 - mu, d3 = x3 - mu;
      float var = warp_sum(d0 * d0 + d1 * d1 + d2 * d2 + d3 * d3) * (1.f / CDIM);
      float rstd = rsqrtf(var + EPSV);
      float o0 = d0 * rstd * wv.x + bv.x, o1 = d1 * rstd * wv.y + bv.y;
      float o2 = d2 * rstd * wv.z + bv.z, o3 = d3 * rstd * wv.w + bv.w;
      float h0 = __half2float(__float2half_rn(o0));
      float h1 = __half2float(__float2half_rn(o1));
      float h2 = __half2float(__float2half_rn(o2));
      float h3 = __half2float(__float2half_rn(o3));
      uint32_t off = KO_SA + jj * 256 + (((l >> 1) ^ (jj & 7)) * 16) + (l & 1) * 8;
      *(uint2*)(smem + off) = make_uint2(pack2h(h0, h1), pack2h(h2, h3));
      *(uint2*)(smem + off + KO_SA_BYTES) =
          make_uint2(pack2h(o0 - h0, o1 - h1), pack2h(o2 - h2, o3 - h3));
    }
  }
  CP_WAIT(0);
  __syncthreads();

  // MMA: M=64 (jj), N=128 (out ch), K=128 (c); 2(M)x4(N) warps, 2 terms
  const int a_r = l & 15, a_c = l >> 4;
  const int b_r = (l & 7) + ((l >> 4) << 3), b_c = (l >> 3) & 1;
  const int wm = w & 1, wn = w >> 1;

  float acc[2][4][4];
#pragma unroll
  for (int mt = 0; mt < 2; mt++)
#pragma unroll
    for (int nt = 0; nt < 4; nt++)
#pragma unroll
      for (int q = 0; q < 4; q++) acc[mt][nt][q] = 0.f;

#pragma unroll
  for (int e = 0; e < 8; e++) {
    uint32_t ah[2][4], al[2][4], bh[2][4];
#pragma unroll
    for (int mt = 0; mt < 2; mt++) {
      int row = wm * 32 + mt * 16 + a_r;
      uint32_t addr = sbase + KO_SA + row * 256 + (((e * 2 + a_c) ^ (row & 7)) * 16);
      LDSM_X4(ah[mt][0], ah[mt][1], ah[mt][2], ah[mt][3], addr);
      LDSM_X4(al[mt][0], al[mt][1], al[mt][2], al[mt][3], addr + KO_SA_BYTES);
    }
#pragma unroll
    for (int np = 0; np < 2; np++) {
      int row = wn * 32 + np * 16 + b_r;
      uint32_t addr = sbase + KO_SW + row * 256 + (((e * 2 + b_c) ^ (row & 7)) * 16);
      LDSM_X4(bh[np][0], bh[np][1], bh[np][2], bh[np][3], addr);
    }
#pragma unroll
    for (int mt = 0; mt < 2; mt++)
#pragma unroll
      for (int nt = 0; nt < 4; nt++) {
        uint32_t h0 = (nt & 1) ? bh[nt >> 1][2] : bh[nt >> 1][0];
        uint32_t h1 = (nt & 1) ? bh[nt >> 1][3] : bh[nt >> 1][1];
        MMAH16816(acc[mt][nt], ah[mt], h0, h1);
        MMAH16816(acc[mt][nt], al[mt], h0, h1);
      }
  }

  // epilogue: out[n][ch] = acc * g * mask
#pragma unroll
  for (int mt = 0; mt < 2; mt++) {
#pragma unroll
    for (int h = 0; h < 2; h++) {
      int jj = wm * 32 + mt * 16 + (l >> 2) + 8 * h;
      size_t n = (size_t)i * LDIM + j0 + jj;
      float mkv = (float)mask[n];
      float* dst = out + n * CDIM + wn * 32 + 2 * (l & 3);
      const float* gsrc = d_g + n * CDIM + wn * 32 + 2 * (l & 3);
#pragma unroll
      for (int nt = 0; nt < 4; nt++) {
        float2 g2 = *(const float2*)(gsrc + nt * 8);
        float2 o = make_float2(acc[mt][nt][2 * h] * g2.x * mkv,
                               acc[mt][nt][2 * h + 1] * g2.y * mkv);
        *(float2*)(dst + nt * 8) = o;
      }
    }
  }
}

// ---------------- launch ----------------------------------------------------
extern "C" void kernel_launch(void* const* d_in, const int* in_sizes, int n_in,
                              void* d_out, int out_size) {
  const float* z        = (const float*)d_in[0];
  const int*   mask     = (const int*)  d_in[1];
  const float* ln_in_w  = (const float*)d_in[2];
  const float* ln_in_b  = (const float*)d_in[3];
  const float* ln_out_w = (const float*)d_in[4];
  const float* ln_out_b = (const float*)d_in[5];
  const float* Wpa = (const float*)d_in[6];
  const float* Wga = (const float*)d_in[7];
  const float* Wpb = (const float*)d_in[8];
  const float* Wgb = (const float*)d_in[9];
  const float* Wgo = (const float*)d_in[10];
  const float* Wpo = (const float*)d_in[11];
  float* out = (float*)d_out;

  cudaFuncSetAttribute(k_projmma, cudaFuncAttributeMaxDynamicSharedMemorySize, PROJ_SMEM);
  cudaFuncSetAttribute(k_einsum_mma, cudaFuncAttributeMaxDynamicSharedMemorySize, EIN_SMEM);
  cudaFuncSetAttribute(k_outmma, cudaFuncAttributeMaxDynamicSharedMemorySize, KO_SMEM);

  k_prew<<<dim3(8, 6), 256>>>(Wga, Wpa, Wgb, Wpb, Wgo, Wpo);
  k_projmma<<<NROWS / 64, 256, PROJ_SMEM>>>(z, mask, ln_in_w, ln_in_b);
  dim3 g2(LDIM / 128, LDIM / 128, CDIM);
  k_einsum_mma<<<g2, 256, EIN_SMEM>>>();
  dim3 g3(LDIM / 64, LDIM);
  k_outmma<<<g3, 256, KO_SMEM>>>(ln_out_w, ln_out_b, mask, out);
}